// round 14
// baseline (speedup 1.0000x reference)
#include <cuda_runtime.h>
#include <cstdint>

#define LSEQ 4096

// ----------------------------- scratch ------------------------------------
__device__ float g_xz[4*256*LSEQ];        // in_proj output (b, 2d, l)
__device__ float g_xc[2][4*128*LSEQ];     // conv+silu per dir (dir1 in flipped space)
__device__ float g_BC[2][4*LSEQ*32];      // (b, l, [Bm16|Cm16]) transposed for scan
__device__ float g_delta[2][4*128*LSEQ];  // softplus(dt@dtproj + b)
__device__ float g_y[2][4*128*LSEQ];      // scan outputs per dir
__device__ float g_outp[4*LSEQ*64];       // out_proj result (b, l, c) == x_recon
__device__ float g_x3[4*64*LSEQ];         // conv3d + bias + residual
__device__ float g_Wf[2][128*160];        // fused weights, K-MAJOR: [dir][k*160+e]
__device__ float g_wT[27*64*64];          // proj_w transposed [tap][ci][co]
__device__ float g_P[2*4*32*2048];        // chunk transfer: product of dA
__device__ float g_q[2*4*32*2048];        // chunk transfer: local final state
__device__ float g_h0[2*4*32*2048];       // per-chunk starting state

__device__ __forceinline__ float ex2f_(float x) {
    float y; asm("ex2.approx.ftz.f32 %0, %1;" : "=f"(y) : "f"(x)); return y;
}
__device__ __forceinline__ float lg2f_(float x) {
    float y; asm("lg2.approx.f32 %0, %1;" : "=f"(y) : "f"(x)); return y;
}
__device__ __forceinline__ float siluf(float v) {
    return __fdividef(v, 1.f + ex2f_(-1.44269504f * v));
}

// packed dual-FMA (Blackwell f32x2): d = a*b + d
__device__ __forceinline__ void fma2(float2& d, const float2& a, const float2& b) {
    unsigned long long& du = reinterpret_cast<unsigned long long&>(d);
    const unsigned long long& au = reinterpret_cast<const unsigned long long&>(a);
    const unsigned long long& bu = reinterpret_cast<const unsigned long long&>(b);
    asm("fma.rn.f32x2 %0, %1, %2, %0;" : "+l"(du) : "l"(au), "l"(bu));
}
__device__ __forceinline__ float2 dup2(float a) { return make_float2(a, a); }

__device__ __forceinline__ uint32_t smem_u32(const void* p) {
    uint32_t a;
    asm("{ .reg .u64 t; cvta.to.shared.u64 t, %1; cvt.u32.u64 %0, t; }" : "=r"(a) : "l"(p));
    return a;
}
#define CP16(dst, src) asm volatile("cp.async.ca.shared.global [%0], [%1], 16;" :: "r"(dst), "l"(src) : "memory")
#define CP_COMMIT()    asm volatile("cp.async.commit_group;" ::: "memory")
#define CP_WAIT1()     asm volatile("cp.async.wait_group 1;" ::: "memory")
#define CP_WAIT0()     asm volatile("cp.async.wait_group 0;" ::: "memory")

// ------------------------- K0: weight prep --------------------------------
__global__ void k_prep(const float* __restrict__ xp0, const float* __restrict__ dt0,
                       const float* __restrict__ xp1, const float* __restrict__ dt1,
                       const float* __restrict__ proj_w) {
    int idx = blockIdx.x*256 + threadIdx.x;
    const int NWF = 2*160*128;
    if (idx < NWF) {
        int dir = idx / (160*128);
        int r = idx % (160*128);
        int e = r >> 7, k = r & 127;
        const float* xp = dir ? xp1 : xp0;
        float v;
        if (e < 32) {
            v = xp[(8+e)*128 + k];                     // rows 8..39 of x_dbl = Bm,Cm
        } else {
            const float* dtw = dir ? dt1 : dt0;
            int d = e - 32; v = 0.f;
            #pragma unroll
            for (int rr = 0; rr < 8; rr++) v = fmaf(dtw[d*8+rr], xp[rr*128+k], v);
        }
        g_Wf[dir][k*160 + e] = v;                      // K-MAJOR
    } else if (idx < NWF + 27*4096) {
        int j = idx - NWF;
        int tap = j >> 12, rest = j & 4095;
        int ci = rest >> 6, co = rest & 63;
        g_wT[j] = proj_w[(co*64 + ci)*27 + tap];       // [tap][ci][co]
    }
}

// ------------------------- K1: in_proj GEMM with seq gather ----------------
__global__ void k_inproj(const float* __restrict__ x, const float* __restrict__ W) {
    __shared__ float S[64*64];      // [c][l_local]
    __shared__ float Wt[64*65];     // [e][c] padded
    int b = blockIdx.z, e0 = blockIdx.y*64, l0 = blockIdx.x*64;
    int h = l0 >> 8, w0 = (l0 >> 4) & 15;
    int tid = threadIdx.x;
    for (int i = tid; i < 4096; i += 256) {
        int c = i >> 6, r = i & 63;
        int wl = r & 3, t = r >> 2;
        S[c*64 + wl*16 + t] = x[(b*64+c)*4096 + t*256 + h*16 + w0 + wl];
    }
    for (int i = tid; i < 4096; i += 256) {
        int e = i >> 6, c = i & 63;
        Wt[e*65 + c] = W[(e0+e)*64 + c];
    }
    __syncthreads();
    int te = tid >> 4, tl = tid & 15;
    float2 acc[4][2] = {};
    #pragma unroll 4
    for (int k = 0; k < 64; k++) {
        float4 b4 = *(const float4*)&S[k*64 + tl*4];
        float2 b01 = make_float2(b4.x, b4.y), b23 = make_float2(b4.z, b4.w);
        #pragma unroll
        for (int i = 0; i < 4; i++) {
            float2 a = dup2(Wt[(te*4+i)*65 + k]);
            fma2(acc[i][0], a, b01);
            fma2(acc[i][1], a, b23);
        }
    }
    #pragma unroll
    for (int i = 0; i < 4; i++) {
        int e = e0 + te*4 + i;
        *(float4*)&g_xz[(b*256+e)*4096 + l0 + tl*4] =
            make_float4(acc[i][0].x, acc[i][0].y, acc[i][1].x, acc[i][1].y);
    }
}

// ------------------------- K2: causal dwconv + silu (4 l / thread) ---------
__global__ void k_conv(const float* __restrict__ cw0, const float* __restrict__ cb0,
                       const float* __restrict__ cw1, const float* __restrict__ cb1) {
    int idx = blockIdx.x*256 + threadIdx.x;      // 2^20 total
    int l4  = (idx & 1023) * 4;
    int d   = (idx >> 10) & 127;
    int b   = (idx >> 17) & 3;
    int dir = idx >> 19;
    const float* row = g_xz + (b*256 + d)*4096;
    const float* cw = dir ? cw1 : cw0;
    float w0 = cw[d*4], w1 = cw[d*4+1], w2 = cw[d*4+2], w3 = cw[d*4+3];
    float bias = (dir ? cb1 : cb0)[d];
    float v[4];
    if (dir == 0) {
        float4 A = (l4 >= 4) ? *(const float4*)&row[l4-4] : make_float4(0,0,0,0);
        float4 C = *(const float4*)&row[l4];
        float xm[8] = {A.x, A.y, A.z, A.w, C.x, C.y, C.z, C.w};   // l4-4 .. l4+3
        #pragma unroll
        for (int j = 0; j < 4; j++)
            v[j] = bias + w0*xm[j+1] + w1*xm[j+2] + w2*xm[j+3] + w3*xm[j+4];
    } else {
        int m = 4092 - l4;                    // row[m..m+6] needed (descending seq)
        float4 A = *(const float4*)&row[m];
        float4 C = (l4 >= 4) ? *(const float4*)&row[m+4] : make_float4(0,0,0,0);
        float ym[8] = {A.x, A.y, A.z, A.w, C.x, C.y, C.z, C.w};   // row[4092-l4 + i]
        #pragma unroll
        for (int j = 0; j < 4; j++)
            v[j] = bias + w0*ym[6-j] + w1*ym[5-j] + w2*ym[4-j] + w3*ym[3-j];
    }
    *(float4*)&g_xc[dir][(b*128+d)*4096 + l4] =
        make_float4(siluf(v[0]), siluf(v[1]), siluf(v[2]), siluf(v[3]));
}

// --------- K3: fused xproj/dtproj GEMM, cp.async double-buffered -----------
// CTA tile 32r x 256l. s_w: all 128 k duplicated (32KB). s_x: 2 x 16k x 256l.
__global__ void __launch_bounds__(256, 3)
k_xproj(const float* __restrict__ dtb0, const float* __restrict__ dtb1) {
    extern __shared__ float sm[];
    float* s_w = sm;                 // [128][64] dup   (8192 f)
    float* s_x0 = sm + 8192;         // [16][256]       (4096 f)
    float* s_x1 = sm + 12288;        // [16][256]       (4096 f)
    int db = blockIdx.z;             // dir*4 + b
    int dir = db >> 2, b = db & 3;
    int r0 = blockIdx.y * 32;
    int l0 = blockIdx.x * 256;
    int tid = threadIdx.x;
    int tr = tid >> 6, tl = tid & 63;

    for (int i = tid; i < 8192; i += 256) {
        int k = i >> 6, rr = i & 63;
        s_w[i] = g_Wf[dir][k*160 + r0 + (rr >> 1)];
    }
    // prefetch chunk 0
    #pragma unroll
    for (int q = 0; q < 4; q++) {
        int i = tid*4 + q*1024;
        int k = i >> 8, ll = i & 255;
        CP16(smem_u32(&s_x0[i]), &g_xc[dir][(b*128 + k)*4096 + l0 + ll]);
    }
    CP_COMMIT();

    float2 acc[8][2] = {};
    for (int c = 0; c < 8; c++) {
        __syncthreads();             // everyone done with buf (c+1)&1's previous use
        if (c < 7) {
            float* nbuf = ((c+1) & 1) ? s_x1 : s_x0;
            int kc = (c+1)*16;
            #pragma unroll
            for (int q = 0; q < 4; q++) {
                int i = tid*4 + q*1024;
                int k = i >> 8, ll = i & 255;
                CP16(smem_u32(&nbuf[i]), &g_xc[dir][(b*128 + kc + k)*4096 + l0 + ll]);
            }
            CP_COMMIT();
            CP_WAIT1();              // chunk c landed
        } else {
            CP_WAIT0();
        }
        __syncthreads();
        const float* sx = (c & 1) ? s_x1 : s_x0;
        const float* sw = &s_w[c*16*64];
        #pragma unroll 8
        for (int k = 0; k < 16; k++) {
            float4 b4 = *(const float4*)&sx[k*256 + tl*4];
            float2 bp0 = make_float2(b4.x, b4.y);
            float2 bp1 = make_float2(b4.z, b4.w);
            const float4* wa = (const float4*)&sw[k*64 + tr*16];
            float4 q0 = wa[0], q1 = wa[1], q2 = wa[2], q3 = wa[3];
            float2 a0 = make_float2(q0.x, q0.y), a1 = make_float2(q0.z, q0.w);
            float2 a2 = make_float2(q1.x, q1.y), a3 = make_float2(q1.z, q1.w);
            float2 a4 = make_float2(q2.x, q2.y), a5 = make_float2(q2.z, q2.w);
            float2 a6 = make_float2(q3.x, q3.y), a7 = make_float2(q3.z, q3.w);
            fma2(acc[0][0], a0, bp0); fma2(acc[0][1], a0, bp1);
            fma2(acc[1][0], a1, bp0); fma2(acc[1][1], a1, bp1);
            fma2(acc[2][0], a2, bp0); fma2(acc[2][1], a2, bp1);
            fma2(acc[3][0], a3, bp0); fma2(acc[3][1], a3, bp1);
            fma2(acc[4][0], a4, bp0); fma2(acc[4][1], a4, bp1);
            fma2(acc[5][0], a5, bp0); fma2(acc[5][1], a5, bp1);
            fma2(acc[6][0], a6, bp0); fma2(acc[6][1], a6, bp1);
            fma2(acc[7][0], a7, bp0); fma2(acc[7][1], a7, bp1);
        }
    }
    const float* dtb = dir ? dtb1 : dtb0;
    int lb = l0 + tl*4;
    if (r0 == 0) {
        #pragma unroll
        for (int i = 0; i < 8; i++) {
            int rg = tr*8 + i;
            float vv[4] = {acc[i][0].x, acc[i][0].y, acc[i][1].x, acc[i][1].y};
            #pragma unroll
            for (int j = 0; j < 4; j++)
                g_BC[dir][(b*4096 + lb + j)*32 + rg] = vv[j];
        }
    } else {
        #pragma unroll
        for (int i = 0; i < 8; i++) {
            int d = r0 + tr*8 + i - 32;
            float bias = dtb[d];
            float vv[4] = {acc[i][0].x, acc[i][0].y, acc[i][1].x, acc[i][1].y};
            #pragma unroll
            for (int j = 0; j < 4; j++) {
                float sarg = vv[j] + bias;
                vv[j] = (sarg > 20.f) ? sarg
                      : 0.69314718056f * lg2f_(1.f + ex2f_(sarg * 1.44269504f));
            }
            *(float4*)&g_delta[dir][(b*128+d)*4096 + lb] =
                make_float4(vv[0], vv[1], vv[2], vv[3]);
        }
    }
}

// ------------------------- K4a: scan pass A (chunk transfer fns) ------------
__global__ void k_scanA(const float* __restrict__ Al0, const float* __restrict__ Al1) {
    __shared__ float s_b[128*16];
    __shared__ float s_d[16*128];
    __shared__ float s_u[16*128];
    int chunk = blockIdx.x >> 3;
    int dg0 = (blockIdx.x & 7) * 16;
    int b = blockIdx.y, dir = blockIdx.z;
    int l0 = chunk * 128;
    int tid = threadIdx.x;
    int wid = tid >> 5, lane = tid & 31;
    int ch = lane >> 4, n = lane & 15;
    int dloc = wid*2 + ch;
    int d = dg0 + dloc;
    const float* Alog = dir ? Al1 : Al0;
    float A2 = -__expf(Alog[d*16 + n]) * 1.44269504089f;
    const float* bc_src = g_BC[dir]    + b*4096*32 + l0*32;
    const float* d_src  = g_delta[dir] + b*128*4096;
    const float* u_src  = g_xc[dir]    + b*128*4096;
    for (int i = tid; i < 2048; i += 256) s_b[i] = bc_src[(i >> 4)*32 + (i & 15)];
    for (int i = tid; i < 2048; i += 256) {
        int dd = i >> 7, s = i & 127;
        s_d[i] = d_src[(dg0+dd)*4096 + l0 + s];
        s_u[i] = u_src[(dg0+dd)*4096 + l0 + s];
    }
    __syncthreads();
    float h = 0.f, P = 1.f;
    const float* pd = &s_d[dloc*128];
    const float* pu = &s_u[dloc*128];
    for (int s4 = 0; s4 < 128; s4 += 4) {
        float4 d4 = *(const float4*)&pd[s4];
        float4 u4 = *(const float4*)&pu[s4];
        float dl[4] = {d4.x, d4.y, d4.z, d4.w};
        float uv[4] = {u4.x, u4.y, u4.z, u4.w};
        #pragma unroll
        for (int q = 0; q < 4; q++) {
            float bv = s_b[(s4+q)*16 + n];
            float dA = ex2f_(dl[q] * A2);
            h = fmaf(dA, h, dl[q] * bv * uv[q]);
            P *= dA;
        }
    }
    int idx = ((dir*4+b)*32 + chunk)*2048 + d*16 + n;
    g_P[idx] = P;
    g_q[idx] = h;
}

// ------------------------- K4b: scan pass B (cross-chunk combine) -----------
__global__ void k_scanB() {
    int db = blockIdx.y;
    int dn = blockIdx.x*256 + threadIdx.x;
    int base = db*32*2048 + dn;
    float h = 0.f;
    #pragma unroll
    for (int c = 0; c < 32; c++) {
        g_h0[base + c*2048] = h;
        h = fmaf(g_P[base + c*2048], h, g_q[base + c*2048]);
    }
}

// ------------------------- K4c: scan pass C (replay, smem-batched reduce) ---
__global__ void k_scanC(const float* __restrict__ Al0, const float* __restrict__ Dp0,
                        const float* __restrict__ Al1, const float* __restrict__ Dp1) {
    __shared__ float s_bc[128*32];
    __shared__ float s_d[16*128];
    __shared__ float s_u[16*128];
    __shared__ float s_p[8*672];
    int chunk = blockIdx.x >> 3;
    int dg0 = (blockIdx.x & 7) * 16;
    int b = blockIdx.y, dir = blockIdx.z;
    int l0 = chunk * 128;
    int tid = threadIdx.x;
    int wid = tid >> 5, lane = tid & 31;
    int ch = lane >> 4, n = lane & 15;
    int dloc = wid*2 + ch;
    int d = dg0 + dloc;
    const float* Alog = dir ? Al1 : Al0;
    const float* Dp   = dir ? Dp1 : Dp0;
    float A2 = -__expf(Alog[d*16 + n]) * 1.44269504089f;
    float Dv = Dp[d];
    const float* bc_src = g_BC[dir]    + b*4096*32 + l0*32;
    const float* d_src  = g_delta[dir] + b*128*4096;
    const float* u_src  = g_xc[dir]    + b*128*4096;
    float*       y_dst  = g_y[dir]     + b*128*4096;
    for (int i = tid; i < 4096; i += 256) s_bc[i] = bc_src[i];
    for (int i = tid; i < 2048; i += 256) {
        int dd = i >> 7, s = i & 127;
        s_d[i] = d_src[(dg0+dd)*4096 + l0 + s];
        s_u[i] = u_src[(dg0+dd)*4096 + l0 + s];
    }
    __syncthreads();
    float h = g_h0[((dir*4+b)*32 + chunk)*2048 + d*16 + n];
    const float* pd = &s_d[dloc*128];
    const float* pu = &s_u[dloc*128];
    float* pbase = &s_p[wid*672 + ch*336];

    for (int sb = 0; sb < 128; sb += 16) {
        #pragma unroll
        for (int s4 = 0; s4 < 16; s4 += 4) {
            float4 d4 = *(const float4*)&pd[sb + s4];
            float4 u4 = *(const float4*)&pu[sb + s4];
            float dl[4] = {d4.x, d4.y, d4.z, d4.w};
            float uv[4] = {u4.x, u4.y, u4.z, u4.w};
            #pragma unroll
            for (int q = 0; q < 4; q++) {
                int s = sb + s4 + q;
                float bv = s_bc[s*32 + n];
                float cv = s_bc[s*32 + 16 + n];
                float dA = ex2f_(dl[q] * A2);
                h = fmaf(dA, h, dl[q] * bv * uv[q]);
                pbase[(s4+q)*20 + n] = h * cv;
            }
        }
        __syncwarp();
        {
            const float4* pr = (const float4*)&pbase[n*20];
            float4 r0 = pr[0], r1 = pr[1], r2 = pr[2], r3 = pr[3];
            float sum = ((r0.x + r0.y) + (r0.z + r0.w))
                      + ((r1.x + r1.y) + (r1.z + r1.w))
                      + ((r2.x + r2.y) + (r2.z + r2.w))
                      + ((r3.x + r3.y) + (r3.z + r3.w));
            float uv = pu[sb + n];
            y_dst[(dg0+dloc)*4096 + l0 + sb + n] = fmaf(uv, Dv, sum);
        }
        __syncwarp();
    }
}

// ------------------------- K5: combine + out_proj (f32x2) ------------------
__global__ void k_outproj(const float* __restrict__ opw) {
    __shared__ float s_c[64*64];
    __shared__ float s_w[64*65];
    int b = blockIdx.y;
    int l0 = blockIdx.x*64;
    int tid = threadIdx.x;
    int tc = tid >> 4, tl = tid & 15;
    float2 acc[4][2] = {};
    for (int d0 = 0; d0 < 128; d0 += 64) {
        __syncthreads();
        for (int i = tid; i < 4096; i += 256) {
            int dd = i >> 6, ll = i & 63;
            int d = d0 + dd, l = l0 + ll;
            float y0 = g_y[0][(b*128+d)*4096 + l];
            float y1 = g_y[1][(b*128+d)*4096 + (4095 - l)];
            float z  = g_xz[(b*256 + 128 + d)*4096 + l];
            s_c[i] = (y0 + y1) * siluf(z);
        }
        for (int i = tid; i < 4096; i += 256) {
            int c = i >> 6, dd = i & 63;
            s_w[c*65 + dd] = opw[c*128 + d0 + dd];
        }
        __syncthreads();
        #pragma unroll 4
        for (int kk = 0; kk < 64; kk++) {
            float4 b4 = *(const float4*)&s_c[kk*64 + tl*4];
            float2 b01 = make_float2(b4.x, b4.y), b23 = make_float2(b4.z, b4.w);
            #pragma unroll
            for (int i = 0; i < 4; i++) {
                float2 a = dup2(s_w[(tc*4+i)*65 + kk]);
                fma2(acc[i][0], a, b01);
                fma2(acc[i][1], a, b23);
            }
        }
    }
    #pragma unroll
    for (int j = 0; j < 4; j++) {
        int l = l0 + tl*4 + j;
        float v0 = (j < 2) ? ((j & 1) ? acc[0][0].y : acc[0][0].x) : ((j & 1) ? acc[0][1].y : acc[0][1].x);
        float v1 = (j < 2) ? ((j & 1) ? acc[1][0].y : acc[1][0].x) : ((j & 1) ? acc[1][1].y : acc[1][1].x);
        float v2 = (j < 2) ? ((j & 1) ? acc[2][0].y : acc[2][0].x) : ((j & 1) ? acc[2][1].y : acc[2][1].x);
        float v3 = (j < 2) ? ((j & 1) ? acc[3][0].y : acc[3][0].x) : ((j & 1) ? acc[3][1].y : acc[3][1].x);
        *(float4*)&g_outp[b*262144 + l*64 + tc*4] = make_float4(v0, v1, v2, v3);
    }
}

// ------------------------- K6: conv3d 3x3x3 + bias + residual --------------
// grid (16 t, 4 b, 4 = co-half x h-half), block 256 = 32 co x 8 rows
__global__ void k_conv3(const float* __restrict__ xres, const float* __restrict__ proj_b) {
    extern __shared__ float s[];
    float* swt = s + 8640;                // [tap27][ci16][co32]
    int t = blockIdx.x, b = blockIdx.y;
    int zz = blockIdx.z;
    int chh = zz >> 1;
    int hh0 = (zz & 1) * 8;
    int tid = threadIdx.x;
    int col = tid & 31;
    int co = chh*32 + col;
    int hg = tid >> 5;                    // 0..7: output row hh0+hg
    float2 acc[8];
    #pragma unroll
    for (int j = 0; j < 8; j++) acc[j] = make_float2(0.f, 0.f);

    for (int cc = 0; cc < 4; cc++) {      // ci chunks of 16
        __syncthreads();
        for (int i = tid; i < 8640; i += 256) {
            int ww = i % 18; int rest = i / 18;
            int hr = rest % 10; rest /= 10;
            int tt = rest % 3; int ci = rest / 3;
            int tg = t + tt - 1, hgl = hh0 + hr - 1, wg = ww - 1;
            float v = 0.f;
            if (tg >= 0 && tg < 16 && hgl >= 0 && hgl < 16 && wg >= 0 && wg < 16)
                v = g_outp[b*262144 + (cc*16+ci)*4096 + tg*256 + hgl*16 + wg];
            s[i] = v;
        }
        for (int j = tid; j < 13824; j += 256) {
            int tap = j >> 9, rest = j & 511;
            int ci = rest >> 5, c = rest & 31;
            swt[j] = g_wT[tap*4096 + (cc*16+ci)*64 + chh*32 + c];
        }
        __syncthreads();
        for (int ci = 0; ci < 16; ci++) {
            #pragma unroll
            for (int kt = 0; kt < 3; kt++) {
                float2 wp[3][3];
                #pragma unroll
                for (int kh = 0; kh < 3; kh++)
                    #pragma unroll
                    for (int kw = 0; kw < 3; kw++)
                        wp[kh][kw] = dup2(swt[((kt*3+kh)*3+kw)*512 + ci*32 + col]);
                int base = ((ci*3 + kt)*10)*18;
                #pragma unroll
                for (int kh = 0; kh < 3; kh++) {
                    const float2* rp = (const float2*)&s[base + (hg + kh)*18];
                    float2 e[9];
                    #pragma unroll
                    for (int q = 0; q < 9; q++) e[q] = rp[q];
                    float2 o[8];
                    #pragma unroll
                    for (int j = 0; j < 8; j++) o[j] = make_float2(e[j].y, e[j+1].x);
                    #pragma unroll
                    for (int j = 0; j < 8; j++) {
                        fma2(acc[j], wp[kh][0], e[j]);
                        fma2(acc[j], wp[kh][1], o[j]);
                        fma2(acc[j], wp[kh][2], e[j+1]);
                    }
                }
            }
        }
    }
    __syncthreads();
    float pb = proj_b[co];
    #pragma unroll
    for (int j = 0; j < 8; j++) {
        s[col*128 + hg*16 + 2*j    ] = acc[j].x + pb;
        s[col*128 + hg*16 + 2*j + 1] = acc[j].y + pb;
    }
    __syncthreads();
    for (int i = tid; i < 4096; i += 256) {
        int cl = i >> 7, p = i & 127;
        int gco = chh*32 + cl;
        int off = (b*64+gco)*4096 + t*256 + hh0*16 + p;
        g_x3[off] = s[i] + xres[off];
    }
}

// ------------------------- K7: 1x1x1 norm conv (f32x2) ---------------------
__global__ void k_norm(const float* __restrict__ nw, const float* __restrict__ nb,
                       float* __restrict__ out) {
    __shared__ float s_x[64*64];
    __shared__ float s_w[64*65];
    int b = blockIdx.y;
    int p0 = blockIdx.x*64;
    int tid = threadIdx.x;
    for (int i = tid; i < 4096; i += 256) {
        int ci = i >> 6, pp = i & 63;
        s_x[i] = g_x3[(b*64+ci)*4096 + p0 + pp];
    }
    for (int i = tid; i < 4096; i += 256) {
        int co = i >> 6, ci = i & 63;
        s_w[co*65 + ci] = nw[i];
    }
    __syncthreads();
    int tc = tid >> 4, tl = tid & 15;
    float2 acc[4][2] = {};
    #pragma unroll 4
    for (int k = 0; k < 64; k++) {
        float4 b4 = *(const float4*)&s_x[k*64 + tl*4];
        float2 b01 = make_float2(b4.x, b4.y), b23 = make_float2(b4.z, b4.w);
        #pragma unroll
        for (int i = 0; i < 4; i++) {
            float2 a = dup2(s_w[(tc*4+i)*65 + k]);
            fma2(acc[i][0], a, b01);
            fma2(acc[i][1], a, b23);
        }
    }
    #pragma unroll
    for (int i = 0; i < 4; i++) {
        int co = tc*4 + i;
        float bb = nb[co];
        *(float4*)&out[(b*64+co)*4096 + p0 + tl*4] =
            make_float4(acc[i][0].x + bb, acc[i][0].y + bb,
                        acc[i][1].x + bb, acc[i][1].y + bb);
    }
}

// ------------------------- launch ------------------------------------------
extern "C" void kernel_launch(void* const* d_in, const int* in_sizes, int n_in,
                              void* d_out, int out_size) {
    const float* x    = (const float*)d_in[0];
    const float* ipw  = (const float*)d_in[1];
    const float* cw0  = (const float*)d_in[2];
    const float* cb0  = (const float*)d_in[3];
    const float* xpw0 = (const float*)d_in[4];
    const float* dtw0 = (const float*)d_in[5];
    const float* dtb0 = (const float*)d_in[6];
    const float* Al0  = (const float*)d_in[7];
    const float* D0   = (const float*)d_in[8];
    const float* cw1  = (const float*)d_in[9];
    const float* cb1  = (const float*)d_in[10];
    const float* xpw1 = (const float*)d_in[11];
    const float* dtw1 = (const float*)d_in[12];
    const float* dtb1 = (const float*)d_in[13];
    const float* Al1  = (const float*)d_in[14];
    const float* D1   = (const float*)d_in[15];
    const float* opw  = (const float*)d_in[16];
    const float* pw   = (const float*)d_in[17];
    const float* pb   = (const float*)d_in[18];
    const float* nw   = (const float*)d_in[19];
    const float* nb   = (const float*)d_in[20];
    float* out = (float*)d_out;

    cudaFuncSetAttribute(k_xproj, cudaFuncAttributeMaxDynamicSharedMemorySize, 16384*4);
    cudaFuncSetAttribute(k_conv3, cudaFuncAttributeMaxDynamicSharedMemorySize, (8640+13824)*4);

    k_prep   <<< (2*160*128 + 27*4096 + 255)/256, 256 >>>(xpw0, dtw0, xpw1, dtw1, pw);
    k_inproj <<< dim3(64, 4, 4), 256 >>>(x, ipw);
    k_conv   <<< (1<<20)/256, 256 >>>(cw0, cb0, cw1, cb1);
    k_xproj  <<< dim3(16, 5, 8), 256, 16384*4 >>>(dtb0, dtb1);
    k_scanA  <<< dim3(256, 4, 2), 256 >>>(Al0, Al1);
    k_scanB  <<< dim3(8, 8), 256 >>>();
    k_scanC  <<< dim3(256, 4, 2), 256 >>>(Al0, D0, Al1, D1);
    k_outproj<<< dim3(64, 4), 256 >>>(opw);
    k_conv3  <<< dim3(16, 4, 4), 256, (8640+13824)*4 >>>(x, pb);
    k_norm   <<< dim3(64, 4), 256 >>>(nw, nb, out);
}

// round 15
// speedup vs baseline: 1.0036x; 1.0036x over previous
#include <cuda_runtime.h>

#define LSEQ 4096

// ----------------------------- scratch ------------------------------------
__device__ float g_xz[4*256*LSEQ];        // in_proj output (b, 2d, l)
__device__ float g_xc[2][4*128*LSEQ];     // conv+silu per dir (dir1 in flipped space)
__device__ float g_BC[2][4*LSEQ*32];      // (b, l, [Bm16|Cm16]) transposed for scan
__device__ float g_delta[2][4*128*LSEQ];  // softplus(dt@dtproj + b)
__device__ float g_y[2][4*128*LSEQ];      // scan outputs per dir
__device__ float g_outp[4*LSEQ*64];       // out_proj result (b, l, c) == x_recon
__device__ float g_x3[4*64*LSEQ];         // conv3d + bias + residual
__device__ float g_Wf[2][128*160];        // fused weights, K-MAJOR: [dir][k*160+e]
__device__ float g_wT[27*64*64];          // proj_w transposed [tap][ci][co]
__device__ float g_P[2*4*32*2048];        // chunk transfer: product of dA
__device__ float g_q[2*4*32*2048];        // chunk transfer: local final state
__device__ float g_h0[2*4*32*2048];       // per-chunk starting state

__device__ __forceinline__ float ex2f_(float x) {
    float y; asm("ex2.approx.ftz.f32 %0, %1;" : "=f"(y) : "f"(x)); return y;
}
__device__ __forceinline__ float lg2f_(float x) {
    float y; asm("lg2.approx.f32 %0, %1;" : "=f"(y) : "f"(x)); return y;
}
__device__ __forceinline__ float siluf(float v) {
    return __fdividef(v, 1.f + ex2f_(-1.44269504f * v));
}

// packed dual-FMA (Blackwell f32x2): d = a*b + d
__device__ __forceinline__ void fma2(float2& d, const float2& a, const float2& b) {
    unsigned long long& du = reinterpret_cast<unsigned long long&>(d);
    const unsigned long long& au = reinterpret_cast<const unsigned long long&>(a);
    const unsigned long long& bu = reinterpret_cast<const unsigned long long&>(b);
    asm("fma.rn.f32x2 %0, %1, %2, %0;" : "+l"(du) : "l"(au), "l"(bu));
}
__device__ __forceinline__ float2 dup2(float a) { return make_float2(a, a); }

// ------------------------- K0: weight prep --------------------------------
__global__ void k_prep(const float* __restrict__ xp0, const float* __restrict__ dt0,
                       const float* __restrict__ xp1, const float* __restrict__ dt1,
                       const float* __restrict__ proj_w) {
    int idx = blockIdx.x*256 + threadIdx.x;
    const int NWF = 2*160*128;
    if (idx < NWF) {
        int dir = idx / (160*128);
        int r = idx % (160*128);
        int e = r >> 7, k = r & 127;
        const float* xp = dir ? xp1 : xp0;
        float v;
        if (e < 32) {
            v = xp[(8+e)*128 + k];                     // rows 8..39 of x_dbl = Bm,Cm
        } else {
            const float* dtw = dir ? dt1 : dt0;
            int d = e - 32; v = 0.f;
            #pragma unroll
            for (int rr = 0; rr < 8; rr++) v = fmaf(dtw[d*8+rr], xp[rr*128+k], v);
        }
        g_Wf[dir][k*160 + e] = v;                      // K-MAJOR
    } else if (idx < NWF + 27*4096) {
        int j = idx - NWF;
        int tap = j >> 12, rest = j & 4095;
        int ci = rest >> 6, co = rest & 63;
        g_wT[j] = proj_w[(co*64 + ci)*27 + tap];       // [tap][ci][co]
    }
}

// ------------------------- K1: in_proj GEMM with seq gather ----------------
__global__ void k_inproj(const float* __restrict__ x, const float* __restrict__ W) {
    __shared__ float S[64*64];      // [c][l_local]
    __shared__ float Wt[64*65];     // [e][c] padded
    int b = blockIdx.z, e0 = blockIdx.y*64, l0 = blockIdx.x*64;
    int h = l0 >> 8, w0 = (l0 >> 4) & 15;
    int tid = threadIdx.x;
    for (int i = tid; i < 4096; i += 256) {
        int c = i >> 6, r = i & 63;
        int wl = r & 3, t = r >> 2;
        S[c*64 + wl*16 + t] = x[(b*64+c)*4096 + t*256 + h*16 + w0 + wl];
    }
    for (int i = tid; i < 4096; i += 256) {
        int e = i >> 6, c = i & 63;
        Wt[e*65 + c] = W[(e0+e)*64 + c];
    }
    __syncthreads();
    int te = tid >> 4, tl = tid & 15;
    float2 acc[4][2] = {};
    #pragma unroll 4
    for (int k = 0; k < 64; k++) {
        float4 b4 = *(const float4*)&S[k*64 + tl*4];
        float2 b01 = make_float2(b4.x, b4.y), b23 = make_float2(b4.z, b4.w);
        #pragma unroll
        for (int i = 0; i < 4; i++) {
            float2 a = dup2(Wt[(te*4+i)*65 + k]);
            fma2(acc[i][0], a, b01);
            fma2(acc[i][1], a, b23);
        }
    }
    #pragma unroll
    for (int i = 0; i < 4; i++) {
        int e = e0 + te*4 + i;
        *(float4*)&g_xz[(b*256+e)*4096 + l0 + tl*4] =
            make_float4(acc[i][0].x, acc[i][0].y, acc[i][1].x, acc[i][1].y);
    }
}

// ------------------------- K2: causal dwconv + silu ------------------------
__global__ void k_conv(const float* __restrict__ cw0, const float* __restrict__ cb0,
                       const float* __restrict__ cw1, const float* __restrict__ cb1) {
    int idx = blockIdx.x*256 + threadIdx.x;      // 2^22 total
    int l   = idx & 4095;
    int d   = (idx >> 12) & 127;
    int b   = (idx >> 19) & 3;
    int dir = idx >> 21;
    const float* row = g_xz + (b*256 + d)*4096;
    float v;
    if (dir == 0) {
        v = cb0[d];
        #pragma unroll
        for (int k = 0; k < 4; k++) { int j = l-3+k; if (j >= 0) v = fmaf(row[j], cw0[d*4+k], v); }
    } else {
        v = cb1[d];
        #pragma unroll
        for (int k = 0; k < 4; k++) { int j = l-3+k; if (j >= 0) v = fmaf(row[4095-j], cw1[d*4+k], v); }
    }
    g_xc[dir][(b*128+d)*4096 + l] = siluf(v);
}

// ------------------------- K3: fused xproj/dtproj GEMM (8r x 4l tile) ------
__global__ void __launch_bounds__(256, 3)
k_xproj(const float* __restrict__ dtb0, const float* __restrict__ dtb1) {
    __shared__ float s_w[32*64];    // [k][r*2 + {0,1}] duplicated
    __shared__ float s_x[32*256];   // [k][l]
    int db = blockIdx.z;            // dir*4 + b
    int dir = db >> 2, b = db & 3;
    int r0 = blockIdx.y * 32;
    int l0 = blockIdx.x * 256;
    int tid = threadIdx.x;
    int tr = tid >> 6, tl = tid & 63;
    float2 acc[8][2] = {};
    for (int kc = 0; kc < 128; kc += 32) {
        __syncthreads();
        for (int i = tid; i < 2048; i += 256) {
            int k = i >> 6, rr = i & 63;
            s_w[i] = g_Wf[dir][(kc+k)*160 + r0 + (rr >> 1)];
        }
        for (int i = tid*4; i < 8192; i += 1024) {
            int k = i >> 8, ll = i & 255;
            *(float4*)&s_x[i] = *(const float4*)&g_xc[dir][(b*128 + kc + k)*4096 + l0 + ll];
        }
        __syncthreads();
        #pragma unroll 8
        for (int k = 0; k < 32; k++) {
            float4 b4 = *(const float4*)&s_x[k*256 + tl*4];
            float2 bp0 = make_float2(b4.x, b4.y);
            float2 bp1 = make_float2(b4.z, b4.w);
            const float4* wa = (const float4*)&s_w[k*64 + tr*16];
            float4 w0 = wa[0], w1 = wa[1], w2 = wa[2], w3 = wa[3];
            float2 a0 = make_float2(w0.x, w0.y), a1 = make_float2(w0.z, w0.w);
            float2 a2 = make_float2(w1.x, w1.y), a3 = make_float2(w1.z, w1.w);
            float2 a4 = make_float2(w2.x, w2.y), a5 = make_float2(w2.z, w2.w);
            float2 a6 = make_float2(w3.x, w3.y), a7 = make_float2(w3.z, w3.w);
            fma2(acc[0][0], a0, bp0); fma2(acc[0][1], a0, bp1);
            fma2(acc[1][0], a1, bp0); fma2(acc[1][1], a1, bp1);
            fma2(acc[2][0], a2, bp0); fma2(acc[2][1], a2, bp1);
            fma2(acc[3][0], a3, bp0); fma2(acc[3][1], a3, bp1);
            fma2(acc[4][0], a4, bp0); fma2(acc[4][1], a4, bp1);
            fma2(acc[5][0], a5, bp0); fma2(acc[5][1], a5, bp1);
            fma2(acc[6][0], a6, bp0); fma2(acc[6][1], a6, bp1);
            fma2(acc[7][0], a7, bp0); fma2(acc[7][1], a7, bp1);
        }
    }
    const float* dtb = dir ? dtb1 : dtb0;
    int lb = l0 + tl*4;
    if (r0 == 0) {
        #pragma unroll
        for (int i = 0; i < 8; i++) {
            int rg = tr*8 + i;
            float vv[4] = {acc[i][0].x, acc[i][0].y, acc[i][1].x, acc[i][1].y};
            #pragma unroll
            for (int j = 0; j < 4; j++)
                g_BC[dir][(b*4096 + lb + j)*32 + rg] = vv[j];
        }
    } else {
        #pragma unroll
        for (int i = 0; i < 8; i++) {
            int d = r0 + tr*8 + i - 32;
            float bias = dtb[d];
            float vv[4] = {acc[i][0].x, acc[i][0].y, acc[i][1].x, acc[i][1].y};
            #pragma unroll
            for (int j = 0; j < 4; j++) {
                float sarg = vv[j] + bias;
                vv[j] = (sarg > 20.f) ? sarg
                      : 0.69314718056f * lg2f_(1.f + ex2f_(sarg * 1.44269504f));
            }
            *(float4*)&g_delta[dir][(b*128+d)*4096 + lb] =
                make_float4(vv[0], vv[1], vv[2], vv[3]);
        }
    }
}

// ------------------------- K4a: scan pass A (chunk transfer fns) ------------
__global__ void k_scanA(const float* __restrict__ Al0, const float* __restrict__ Al1) {
    __shared__ float s_b[128*16];
    __shared__ float s_d[16*128];
    __shared__ float s_u[16*128];
    int chunk = blockIdx.x >> 3;
    int dg0 = (blockIdx.x & 7) * 16;
    int b = blockIdx.y, dir = blockIdx.z;
    int l0 = chunk * 128;
    int tid = threadIdx.x;
    int wid = tid >> 5, lane = tid & 31;
    int ch = lane >> 4, n = lane & 15;
    int dloc = wid*2 + ch;
    int d = dg0 + dloc;
    const float* Alog = dir ? Al1 : Al0;
    float A2 = -__expf(Alog[d*16 + n]) * 1.44269504089f;
    const float* bc_src = g_BC[dir]    + b*4096*32 + l0*32;
    const float* d_src  = g_delta[dir] + b*128*4096;
    const float* u_src  = g_xc[dir]    + b*128*4096;
    for (int i = tid; i < 2048; i += 256) s_b[i] = bc_src[(i >> 4)*32 + (i & 15)];
    for (int i = tid; i < 2048; i += 256) {
        int dd = i >> 7, s = i & 127;
        s_d[i] = d_src[(dg0+dd)*4096 + l0 + s];
        s_u[i] = u_src[(dg0+dd)*4096 + l0 + s];
    }
    __syncthreads();
    float h = 0.f, P = 1.f;
    const float* pd = &s_d[dloc*128];
    const float* pu = &s_u[dloc*128];
    for (int s4 = 0; s4 < 128; s4 += 4) {
        float4 d4 = *(const float4*)&pd[s4];
        float4 u4 = *(const float4*)&pu[s4];
        float dl[4] = {d4.x, d4.y, d4.z, d4.w};
        float uv[4] = {u4.x, u4.y, u4.z, u4.w};
        #pragma unroll
        for (int q = 0; q < 4; q++) {
            float bv = s_b[(s4+q)*16 + n];
            float dA = ex2f_(dl[q] * A2);
            h = fmaf(dA, h, dl[q] * bv * uv[q]);
            P *= dA;
        }
    }
    int idx = ((dir*4+b)*32 + chunk)*2048 + d*16 + n;
    g_P[idx] = P;
    g_q[idx] = h;
}

// ------------------------- K4b: scan pass B (cross-chunk combine) -----------
__global__ void k_scanB() {
    int db = blockIdx.y;
    int dn = blockIdx.x*256 + threadIdx.x;
    int base = db*32*2048 + dn;
    float h = 0.f;
    #pragma unroll
    for (int c = 0; c < 32; c++) {
        g_h0[base + c*2048] = h;
        h = fmaf(g_P[base + c*2048], h, g_q[base + c*2048]);
    }
}

// ------------------------- K4c: scan pass C (replay, smem-batched reduce) ---
__global__ void k_scanC(const float* __restrict__ Al0, const float* __restrict__ Dp0,
                        const float* __restrict__ Al1, const float* __restrict__ Dp1) {
    __shared__ float s_bc[128*32];
    __shared__ float s_d[16*128];
    __shared__ float s_u[16*128];
    __shared__ float s_p[8*672];
    int chunk = blockIdx.x >> 3;
    int dg0 = (blockIdx.x & 7) * 16;
    int b = blockIdx.y, dir = blockIdx.z;
    int l0 = chunk * 128;
    int tid = threadIdx.x;
    int wid = tid >> 5, lane = tid & 31;
    int ch = lane >> 4, n = lane & 15;
    int dloc = wid*2 + ch;
    int d = dg0 + dloc;
    const float* Alog = dir ? Al1 : Al0;
    const float* Dp   = dir ? Dp1 : Dp0;
    float A2 = -__expf(Alog[d*16 + n]) * 1.44269504089f;
    float Dv = Dp[d];
    const float* bc_src = g_BC[dir]    + b*4096*32 + l0*32;
    const float* d_src  = g_delta[dir] + b*128*4096;
    const float* u_src  = g_xc[dir]    + b*128*4096;
    float*       y_dst  = g_y[dir]     + b*128*4096;
    for (int i = tid; i < 4096; i += 256) s_bc[i] = bc_src[i];
    for (int i = tid; i < 2048; i += 256) {
        int dd = i >> 7, s = i & 127;
        s_d[i] = d_src[(dg0+dd)*4096 + l0 + s];
        s_u[i] = u_src[(dg0+dd)*4096 + l0 + s];
    }
    __syncthreads();
    float h = g_h0[((dir*4+b)*32 + chunk)*2048 + d*16 + n];
    const float* pd = &s_d[dloc*128];
    const float* pu = &s_u[dloc*128];
    float* pbase = &s_p[wid*672 + ch*336];

    for (int sb = 0; sb < 128; sb += 16) {
        #pragma unroll
        for (int s4 = 0; s4 < 16; s4 += 4) {
            float4 d4 = *(const float4*)&pd[sb + s4];
            float4 u4 = *(const float4*)&pu[sb + s4];
            float dl[4] = {d4.x, d4.y, d4.z, d4.w};
            float uv[4] = {u4.x, u4.y, u4.z, u4.w};
            #pragma unroll
            for (int q = 0; q < 4; q++) {
                int s = sb + s4 + q;
                float bv = s_bc[s*32 + n];
                float cv = s_bc[s*32 + 16 + n];
                float dA = ex2f_(dl[q] * A2);
                h = fmaf(dA, h, dl[q] * bv * uv[q]);
                pbase[(s4+q)*20 + n] = h * cv;
            }
        }
        __syncwarp();
        {
            const float4* pr = (const float4*)&pbase[n*20];
            float4 r0 = pr[0], r1 = pr[1], r2 = pr[2], r3 = pr[3];
            float sum = ((r0.x + r0.y) + (r0.z + r0.w))
                      + ((r1.x + r1.y) + (r1.z + r1.w))
                      + ((r2.x + r2.y) + (r2.z + r2.w))
                      + ((r3.x + r3.y) + (r3.z + r3.w));
            float uv = pu[sb + n];
            y_dst[(dg0+dloc)*4096 + l0 + sb + n] = fmaf(uv, Dv, sum);
        }
        __syncwarp();
    }
}

// ------------------------- K5: combine + out_proj (f32x2) ------------------
__global__ void k_outproj(const float* __restrict__ opw) {
    __shared__ float s_c[64*64];
    __shared__ float s_w[64*65];
    int b = blockIdx.y;
    int l0 = blockIdx.x*64;
    int tid = threadIdx.x;
    int tc = tid >> 4, tl = tid & 15;
    float2 acc[4][2] = {};
    for (int d0 = 0; d0 < 128; d0 += 64) {
        __syncthreads();
        for (int i = tid; i < 4096; i += 256) {
            int dd = i >> 6, ll = i & 63;
            int d = d0 + dd, l = l0 + ll;
            float y0 = g_y[0][(b*128+d)*4096 + l];
            float y1 = g_y[1][(b*128+d)*4096 + (4095 - l)];
            float z  = g_xz[(b*256 + 128 + d)*4096 + l];
            s_c[i] = (y0 + y1) * siluf(z);
        }
        for (int i = tid; i < 4096; i += 256) {
            int c = i >> 6, dd = i & 63;
            s_w[c*65 + dd] = opw[c*128 + d0 + dd];
        }
        __syncthreads();
        #pragma unroll 4
        for (int kk = 0; kk < 64; kk++) {
            float4 b4 = *(const float4*)&s_c[kk*64 + tl*4];
            float2 b01 = make_float2(b4.x, b4.y), b23 = make_float2(b4.z, b4.w);
            #pragma unroll
            for (int i = 0; i < 4; i++) {
                float2 a = dup2(s_w[(tc*4+i)*65 + kk]);
                fma2(acc[i][0], a, b01);
                fma2(acc[i][1], a, b23);
            }
        }
    }
    #pragma unroll
    for (int j = 0; j < 4; j++) {
        int l = l0 + tl*4 + j;
        float v0 = (j < 2) ? ((j & 1) ? acc[0][0].y : acc[0][0].x) : ((j & 1) ? acc[0][1].y : acc[0][1].x);
        float v1 = (j < 2) ? ((j & 1) ? acc[1][0].y : acc[1][0].x) : ((j & 1) ? acc[1][1].y : acc[1][1].x);
        float v2 = (j < 2) ? ((j & 1) ? acc[2][0].y : acc[2][0].x) : ((j & 1) ? acc[2][1].y : acc[2][1].x);
        float v3 = (j < 2) ? ((j & 1) ? acc[3][0].y : acc[3][0].x) : ((j & 1) ? acc[3][1].y : acc[3][1].x);
        *(float4*)&g_outp[b*262144 + l*64 + tc*4] = make_float4(v0, v1, v2, v3);
    }
}

// ------------------------- K6: conv3d 3x3x3 + bias + residual --------------
// grid (16 t, 4 b, 4 = co-half x h-half), block 128 = 32 co x 4 row-PAIRS.
// Each thread: 2 adjacent output rows (shares input rows across kh taps).
// ci chunks of 8. dyn smem: input [ci8][kt3][h10][w18]=4320 f, weights
// [tap27][ci8][co32]=6912 f -> 44.9 KB, 4 CTAs/SM.
__global__ void __launch_bounds__(128, 4)
k_conv3(const float* __restrict__ xres, const float* __restrict__ proj_b) {
    extern __shared__ float s[];
    float* swt = s + 4320;
    int t = blockIdx.x, b = blockIdx.y;
    int zz = blockIdx.z;
    int chh = zz >> 1;
    int hh0 = (zz & 1) * 8;
    int tid = threadIdx.x;
    int col = tid & 31;                   // co within half
    int co = chh*32 + col;
    int rg = tid >> 5;                    // 0..3 -> output rows 2rg, 2rg+1
    float2 acc[2][8];
    #pragma unroll
    for (int r = 0; r < 2; r++)
        #pragma unroll
        for (int j = 0; j < 8; j++) acc[r][j] = make_float2(0.f, 0.f);

    for (int cc = 0; cc < 8; cc++) {      // ci chunks of 8
        __syncthreads();
        for (int i = tid; i < 4320; i += 128) {
            int ww = i % 18; int rest = i / 18;
            int hr = rest % 10; rest /= 10;
            int tt = rest % 3; int ci = rest / 3;
            int tg = t + tt - 1, hgl = hh0 + hr - 1, wg = ww - 1;
            float v = 0.f;
            if (tg >= 0 && tg < 16 && hgl >= 0 && hgl < 16 && wg >= 0 && wg < 16)
                v = g_outp[b*262144 + (cc*8+ci)*4096 + tg*256 + hgl*16 + wg];
            s[i] = v;
        }
        for (int j = tid; j < 6912; j += 128) {
            int tap = j >> 8, rest = j & 255;
            int ci = rest >> 5, c = rest & 31;
            swt[j] = g_wT[tap*4096 + (cc*8+ci)*64 + chh*32 + c];
        }
        __syncthreads();
        for (int ci = 0; ci < 8; ci++) {
            #pragma unroll
            for (int kt = 0; kt < 3; kt++) {
                float2 wp[3][3];
                #pragma unroll
                for (int kh = 0; kh < 3; kh++)
                    #pragma unroll
                    for (int kw = 0; kw < 3; kw++)
                        wp[kh][kw] = dup2(swt[((kt*3+kh)*3+kw)*256 + ci*32 + col]);
                int base = ((ci*3 + kt)*10)*18;
                #pragma unroll
                for (int ir = 0; ir < 4; ir++) {       // input rows 2rg+ir
                    const float2* rp = (const float2*)&s[base + (2*rg + ir)*18];
                    float2 e[9];
                    #pragma unroll
                    for (int q = 0; q < 9; q++) e[q] = rp[q];
                    float2 o[8];
                    #pragma unroll
                    for (int j = 0; j < 8; j++) o[j] = make_float2(e[j].y, e[j+1].x);
                    #pragma unroll
                    for (int r = 0; r < 2; r++) {
                        int kh = ir - r;
                        if (kh >= 0 && kh <= 2) {
                            #pragma unroll
                            for (int j = 0; j < 8; j++) {
                                fma2(acc[r][j], wp[kh][0], e[j]);
                                fma2(acc[r][j], wp[kh][1], o[j]);
                                fma2(acc[r][j], wp[kh][2], e[j+1]);
                            }
                        }
                    }
                }
            }
        }
    }
    // stage through smem for coalesced stores + bias + residual
    __syncthreads();
    float pb = proj_b[co];
    #pragma unroll
    for (int r = 0; r < 2; r++)
        #pragma unroll
        for (int j = 0; j < 8; j++) {
            s[col*128 + (2*rg + r)*16 + 2*j    ] = acc[r][j].x + pb;
            s[col*128 + (2*rg + r)*16 + 2*j + 1] = acc[r][j].y + pb;
        }
    __syncthreads();
    for (int i = tid; i < 4096; i += 128) {
        int cl = i >> 7, p = i & 127;
        int gco = chh*32 + cl;
        int off = (b*64+gco)*4096 + t*256 + hh0*16 + p;
        g_x3[off] = s[i] + xres[off];
    }
}

// ------------------------- K7: 1x1x1 norm conv (f32x2) ---------------------
__global__ void k_norm(const float* __restrict__ nw, const float* __restrict__ nb,
                       float* __restrict__ out) {
    __shared__ float s_x[64*64];
    __shared__ float s_w[64*65];
    int b = blockIdx.y;
    int p0 = blockIdx.x*64;
    int tid = threadIdx.x;
    for (int i = tid; i < 4096; i += 256) {
        int ci = i >> 6, pp = i & 63;
        s_x[i] = g_x3[(b*64+ci)*4096 + p0 + pp];
    }
    for (int i = tid; i < 4096; i += 256) {
        int co = i >> 6, ci = i & 63;
        s_w[co*65 + ci] = nw[i];
    }
    __syncthreads();
    int tc = tid >> 4, tl = tid & 15;
    float2 acc[4][2] = {};
    #pragma unroll 4
    for (int k = 0; k < 64; k++) {
        float4 b4 = *(const float4*)&s_x[k*64 + tl*4];
        float2 b01 = make_float2(b4.x, b4.y), b23 = make_float2(b4.z, b4.w);
        #pragma unroll
        for (int i = 0; i < 4; i++) {
            float2 a = dup2(s_w[(tc*4+i)*65 + k]);
            fma2(acc[i][0], a, b01);
            fma2(acc[i][1], a, b23);
        }
    }
    #pragma unroll
    for (int i = 0; i < 4; i++) {
        int co = tc*4 + i;
        float bb = nb[co];
        *(float4*)&out[(b*64+co)*4096 + p0 + tl*4] =
            make_float4(acc[i][0].x + bb, acc[i][0].y + bb,
                        acc[i][1].x + bb, acc[i][1].y + bb);
    }
}

// ------------------------- launch ------------------------------------------
extern "C" void kernel_launch(void* const* d_in, const int* in_sizes, int n_in,
                              void* d_out, int out_size) {
    const float* x    = (const float*)d_in[0];
    const float* ipw  = (const float*)d_in[1];
    const float* cw0  = (const float*)d_in[2];
    const float* cb0  = (const float*)d_in[3];
    const float* xpw0 = (const float*)d_in[4];
    const float* dtw0 = (const float*)d_in[5];
    const float* dtb0 = (const float*)d_in[6];
    const float* Al0  = (const float*)d_in[7];
    const float* D0   = (const float*)d_in[8];
    const float* cw1  = (const float*)d_in[9];
    const float* cb1  = (const float*)d_in[10];
    const float* xpw1 = (const float*)d_in[11];
    const float* dtw1 = (const float*)d_in[12];
    const float* dtb1 = (const float*)d_in[13];
    const float* Al1  = (const float*)d_in[14];
    const float* D1   = (const float*)d_in[15];
    const float* opw  = (const float*)d_in[16];
    const float* pw   = (const float*)d_in[17];
    const float* pb   = (const float*)d_in[18];
    const float* nw   = (const float*)d_in[19];
    const float* nb   = (const float*)d_in[20];
    float* out = (float*)d_out;

    cudaFuncSetAttribute(k_conv3, cudaFuncAttributeMaxDynamicSharedMemorySize, (4320+6912)*4);

    k_prep   <<< (2*160*128 + 27*4096 + 255)/256, 256 >>>(xpw0, dtw0, xpw1, dtw1, pw);
    k_inproj <<< dim3(64, 4, 4), 256 >>>(x, ipw);
    k_conv   <<< (1<<22)/256, 256 >>>(cw0, cb0, cw1, cb1);
    k_xproj  <<< dim3(16, 5, 8), 256 >>>(dtb0, dtb1);
    k_scanA  <<< dim3(256, 4, 2), 256 >>>(Al0, Al1);
    k_scanB  <<< dim3(8, 8), 256 >>>();
    k_scanC  <<< dim3(256, 4, 2), 256 >>>(Al0, D0, Al1, D1);
    k_outproj<<< dim3(64, 4), 256 >>>(opw);
    k_conv3  <<< dim3(16, 4, 4), 128, (4320+6912)*4 >>>(x, pb);
    k_norm   <<< dim3(64, 4), 256 >>>(nw, nb, out);
}

// round 16
// speedup vs baseline: 1.0364x; 1.0326x over previous
#include <cuda_runtime.h>

#define LSEQ 4096

// ----------------------------- scratch ------------------------------------
__device__ float g_xz[4*256*LSEQ];        // in_proj output (b, 2d, l)
__device__ float g_xc[2][4*128*LSEQ];     // conv+silu per dir (dir1 in flipped space)
__device__ float g_BC[2][4*LSEQ*32];      // (b, l, [Bm16|Cm16]) transposed for scan
__device__ float g_delta[2][4*128*LSEQ];  // softplus(dt@dtproj + b)
__device__ float g_y[2][4*128*LSEQ];      // scan outputs per dir
__device__ float g_outp[4*LSEQ*64];       // out_proj result (b, l, c) == x_recon
__device__ float g_x3[4*64*LSEQ];         // conv3d + bias + residual
__device__ float g_Wf[2][128*160];        // fused weights, K-MAJOR: [dir][k*160+e]
__device__ float g_wT[27*64*64];          // proj_w transposed [tap][ci][co]
__device__ float g_P[2*4*32*2048];        // chunk transfer: product of dA
__device__ float g_q[2*4*32*2048];        // chunk transfer: local final state
__device__ float g_h0[2*4*32*2048];       // per-chunk starting state

__device__ __forceinline__ float ex2f_(float x) {
    float y; asm("ex2.approx.ftz.f32 %0, %1;" : "=f"(y) : "f"(x)); return y;
}
__device__ __forceinline__ float lg2f_(float x) {
    float y; asm("lg2.approx.f32 %0, %1;" : "=f"(y) : "f"(x)); return y;
}
__device__ __forceinline__ float siluf(float v) {
    return __fdividef(v, 1.f + ex2f_(-1.44269504f * v));
}

// packed dual-FMA (Blackwell f32x2): d = a*b + d
__device__ __forceinline__ void fma2(float2& d, const float2& a, const float2& b) {
    unsigned long long& du = reinterpret_cast<unsigned long long&>(d);
    const unsigned long long& au = reinterpret_cast<const unsigned long long&>(a);
    const unsigned long long& bu = reinterpret_cast<const unsigned long long&>(b);
    asm("fma.rn.f32x2 %0, %1, %2, %0;" : "+l"(du) : "l"(au), "l"(bu));
}
__device__ __forceinline__ float2 dup2(float a) { return make_float2(a, a); }

// ------------------------- K0: weight prep --------------------------------
__global__ void k_prep(const float* __restrict__ xp0, const float* __restrict__ dt0,
                       const float* __restrict__ xp1, const float* __restrict__ dt1,
                       const float* __restrict__ proj_w) {
    int idx = blockIdx.x*256 + threadIdx.x;
    const int NWF = 2*160*128;
    if (idx < NWF) {
        int dir = idx / (160*128);
        int r = idx % (160*128);
        int e = r >> 7, k = r & 127;
        const float* xp = dir ? xp1 : xp0;
        float v;
        if (e < 32) {
            v = xp[(8+e)*128 + k];                     // rows 8..39 of x_dbl = Bm,Cm
        } else {
            const float* dtw = dir ? dt1 : dt0;
            int d = e - 32; v = 0.f;
            #pragma unroll
            for (int rr = 0; rr < 8; rr++) v = fmaf(dtw[d*8+rr], xp[rr*128+k], v);
        }
        g_Wf[dir][k*160 + e] = v;                      // K-MAJOR
    } else if (idx < NWF + 27*4096) {
        int j = idx - NWF;
        int tap = j >> 12, rest = j & 4095;
        int ci = rest >> 6, co = rest & 63;
        g_wT[j] = proj_w[(co*64 + ci)*27 + tap];       // [tap][ci][co]
    }
}

// ------------------------- K1: in_proj GEMM with seq gather ----------------
__global__ void k_inproj(const float* __restrict__ x, const float* __restrict__ W) {
    __shared__ float S[64*64];      // [c][l_local]
    __shared__ float Wt[64*65];     // [e][c] padded
    int b = blockIdx.z, e0 = blockIdx.y*64, l0 = blockIdx.x*64;
    int h = l0 >> 8, w0 = (l0 >> 4) & 15;
    int tid = threadIdx.x;
    // gather: one float4 per (c,t) covers wl=0..3 (w0 multiple of 4 -> aligned)
    for (int i = tid; i < 1024; i += 256) {
        int c = i >> 4, t = i & 15;
        float4 v = *(const float4*)&x[(b*64+c)*4096 + t*256 + h*16 + w0];
        S[c*64 +      t] = v.x;
        S[c*64 + 16 + t] = v.y;
        S[c*64 + 32 + t] = v.z;
        S[c*64 + 48 + t] = v.w;
    }
    for (int i = tid; i < 4096; i += 256) {
        int e = i >> 6, c = i & 63;
        Wt[e*65 + c] = W[(e0+e)*64 + c];
    }
    __syncthreads();
    int te = tid >> 4, tl = tid & 15;
    float2 acc[4][2] = {};
    #pragma unroll 4
    for (int k = 0; k < 64; k++) {
        float4 b4 = *(const float4*)&S[k*64 + tl*4];
        float2 b01 = make_float2(b4.x, b4.y), b23 = make_float2(b4.z, b4.w);
        #pragma unroll
        for (int i = 0; i < 4; i++) {
            float2 a = dup2(Wt[(te*4+i)*65 + k]);
            fma2(acc[i][0], a, b01);
            fma2(acc[i][1], a, b23);
        }
    }
    #pragma unroll
    for (int i = 0; i < 4; i++) {
        int e = e0 + te*4 + i;
        *(float4*)&g_xz[(b*256+e)*4096 + l0 + tl*4] =
            make_float4(acc[i][0].x, acc[i][0].y, acc[i][1].x, acc[i][1].y);
    }
}

// ------------------------- K2: causal dwconv + silu ------------------------
__global__ void k_conv(const float* __restrict__ cw0, const float* __restrict__ cb0,
                       const float* __restrict__ cw1, const float* __restrict__ cb1) {
    int idx = blockIdx.x*256 + threadIdx.x;      // 2^22 total
    int l   = idx & 4095;
    int d   = (idx >> 12) & 127;
    int b   = (idx >> 19) & 3;
    int dir = idx >> 21;
    const float* row = g_xz + (b*256 + d)*4096;
    float v;
    if (dir == 0) {
        v = cb0[d];
        #pragma unroll
        for (int k = 0; k < 4; k++) { int j = l-3+k; if (j >= 0) v = fmaf(row[j], cw0[d*4+k], v); }
    } else {
        v = cb1[d];
        #pragma unroll
        for (int k = 0; k < 4; k++) { int j = l-3+k; if (j >= 0) v = fmaf(row[4095-j], cw1[d*4+k], v); }
    }
    g_xc[dir][(b*128+d)*4096 + l] = siluf(v);
}

// ------------------------- K3: fused xproj/dtproj GEMM (8r x 4l tile) ------
__global__ void __launch_bounds__(256, 3)
k_xproj(const float* __restrict__ dtb0, const float* __restrict__ dtb1) {
    __shared__ float s_w[32*64];    // [k][r*2 + {0,1}] duplicated
    __shared__ float s_x[32*256];   // [k][l]
    int db = blockIdx.z;            // dir*4 + b
    int dir = db >> 2, b = db & 3;
    int r0 = blockIdx.y * 32;
    int l0 = blockIdx.x * 256;
    int tid = threadIdx.x;
    int tr = tid >> 6, tl = tid & 63;
    float2 acc[8][2] = {};
    for (int kc = 0; kc < 128; kc += 32) {
        __syncthreads();
        for (int i = tid; i < 2048; i += 256) {
            int k = i >> 6, rr = i & 63;
            s_w[i] = g_Wf[dir][(kc+k)*160 + r0 + (rr >> 1)];
        }
        for (int i = tid*4; i < 8192; i += 1024) {
            int k = i >> 8, ll = i & 255;
            *(float4*)&s_x[i] = *(const float4*)&g_xc[dir][(b*128 + kc + k)*4096 + l0 + ll];
        }
        __syncthreads();
        #pragma unroll 8
        for (int k = 0; k < 32; k++) {
            float4 b4 = *(const float4*)&s_x[k*256 + tl*4];
            float2 bp0 = make_float2(b4.x, b4.y);
            float2 bp1 = make_float2(b4.z, b4.w);
            const float4* wa = (const float4*)&s_w[k*64 + tr*16];
            float4 w0 = wa[0], w1 = wa[1], w2 = wa[2], w3 = wa[3];
            float2 a0 = make_float2(w0.x, w0.y), a1 = make_float2(w0.z, w0.w);
            float2 a2 = make_float2(w1.x, w1.y), a3 = make_float2(w1.z, w1.w);
            float2 a4 = make_float2(w2.x, w2.y), a5 = make_float2(w2.z, w2.w);
            float2 a6 = make_float2(w3.x, w3.y), a7 = make_float2(w3.z, w3.w);
            fma2(acc[0][0], a0, bp0); fma2(acc[0][1], a0, bp1);
            fma2(acc[1][0], a1, bp0); fma2(acc[1][1], a1, bp1);
            fma2(acc[2][0], a2, bp0); fma2(acc[2][1], a2, bp1);
            fma2(acc[3][0], a3, bp0); fma2(acc[3][1], a3, bp1);
            fma2(acc[4][0], a4, bp0); fma2(acc[4][1], a4, bp1);
            fma2(acc[5][0], a5, bp0); fma2(acc[5][1], a5, bp1);
            fma2(acc[6][0], a6, bp0); fma2(acc[6][1], a6, bp1);
            fma2(acc[7][0], a7, bp0); fma2(acc[7][1], a7, bp1);
        }
    }
    const float* dtb = dir ? dtb1 : dtb0;
    int lb = l0 + tl*4;
    if (r0 == 0) {
        #pragma unroll
        for (int i = 0; i < 8; i++) {
            int rg = tr*8 + i;
            float vv[4] = {acc[i][0].x, acc[i][0].y, acc[i][1].x, acc[i][1].y};
            #pragma unroll
            for (int j = 0; j < 4; j++)
                g_BC[dir][(b*4096 + lb + j)*32 + rg] = vv[j];
        }
    } else {
        #pragma unroll
        for (int i = 0; i < 8; i++) {
            int d = r0 + tr*8 + i - 32;
            float bias = dtb[d];
            float vv[4] = {acc[i][0].x, acc[i][0].y, acc[i][1].x, acc[i][1].y};
            #pragma unroll
            for (int j = 0; j < 4; j++) {
                float sarg = vv[j] + bias;
                vv[j] = (sarg > 20.f) ? sarg
                      : 0.69314718056f * lg2f_(1.f + ex2f_(sarg * 1.44269504f));
            }
            *(float4*)&g_delta[dir][(b*128+d)*4096 + lb] =
                make_float4(vv[0], vv[1], vv[2], vv[3]);
        }
    }
}

// ------------------------- K4a: scan pass A (chunk transfer fns) ------------
__global__ void k_scanA(const float* __restrict__ Al0, const float* __restrict__ Al1) {
    __shared__ float s_b[128*16];
    __shared__ float s_d[16*128];
    __shared__ float s_u[16*128];
    int chunk = blockIdx.x >> 3;
    int dg0 = (blockIdx.x & 7) * 16;
    int b = blockIdx.y, dir = blockIdx.z;
    int l0 = chunk * 128;
    int tid = threadIdx.x;
    int wid = tid >> 5, lane = tid & 31;
    int ch = lane >> 4, n = lane & 15;
    int dloc = wid*2 + ch;
    int d = dg0 + dloc;
    const float* Alog = dir ? Al1 : Al0;
    float A2 = -__expf(Alog[d*16 + n]) * 1.44269504089f;
    const float* bc_src = g_BC[dir]    + b*4096*32 + l0*32;
    const float* d_src  = g_delta[dir] + b*128*4096;
    const float* u_src  = g_xc[dir]    + b*128*4096;
    for (int i = tid; i < 2048; i += 256) s_b[i] = bc_src[(i >> 4)*32 + (i & 15)];
    for (int i = tid; i < 2048; i += 256) {
        int dd = i >> 7, s = i & 127;
        s_d[i] = d_src[(dg0+dd)*4096 + l0 + s];
        s_u[i] = u_src[(dg0+dd)*4096 + l0 + s];
    }
    __syncthreads();
    float h = 0.f, P = 1.f;
    const float* pd = &s_d[dloc*128];
    const float* pu = &s_u[dloc*128];
    for (int s4 = 0; s4 < 128; s4 += 4) {
        float4 d4 = *(const float4*)&pd[s4];
        float4 u4 = *(const float4*)&pu[s4];
        float dl[4] = {d4.x, d4.y, d4.z, d4.w};
        float uv[4] = {u4.x, u4.y, u4.z, u4.w};
        #pragma unroll
        for (int q = 0; q < 4; q++) {
            float bv = s_b[(s4+q)*16 + n];
            float dA = ex2f_(dl[q] * A2);
            h = fmaf(dA, h, dl[q] * bv * uv[q]);
            P *= dA;
        }
    }
    int idx = ((dir*4+b)*32 + chunk)*2048 + d*16 + n;
    g_P[idx] = P;
    g_q[idx] = h;
}

// ------------------------- K4b: scan pass B (cross-chunk combine) -----------
__global__ void k_scanB() {
    int db = blockIdx.y;
    int dn = blockIdx.x*256 + threadIdx.x;
    int base = db*32*2048 + dn;
    float h = 0.f;
    #pragma unroll
    for (int c = 0; c < 32; c++) {
        g_h0[base + c*2048] = h;
        h = fmaf(g_P[base + c*2048], h, g_q[base + c*2048]);
    }
}

// ------------------------- K4c: scan pass C (replay, smem-batched reduce) ---
__global__ void k_scanC(const float* __restrict__ Al0, const float* __restrict__ Dp0,
                        const float* __restrict__ Al1, const float* __restrict__ Dp1) {
    __shared__ float s_bc[128*32];
    __shared__ float s_d[16*128];
    __shared__ float s_u[16*128];
    __shared__ float s_p[8*672];
    int chunk = blockIdx.x >> 3;
    int dg0 = (blockIdx.x & 7) * 16;
    int b = blockIdx.y, dir = blockIdx.z;
    int l0 = chunk * 128;
    int tid = threadIdx.x;
    int wid = tid >> 5, lane = tid & 31;
    int ch = lane >> 4, n = lane & 15;
    int dloc = wid*2 + ch;
    int d = dg0 + dloc;
    const float* Alog = dir ? Al1 : Al0;
    const float* Dp   = dir ? Dp1 : Dp0;
    float A2 = -__expf(Alog[d*16 + n]) * 1.44269504089f;
    float Dv = Dp[d];
    const float* bc_src = g_BC[dir]    + b*4096*32 + l0*32;
    const float* d_src  = g_delta[dir] + b*128*4096;
    const float* u_src  = g_xc[dir]    + b*128*4096;
    float*       y_dst  = g_y[dir]     + b*128*4096;
    for (int i = tid; i < 4096; i += 256) s_bc[i] = bc_src[i];
    for (int i = tid; i < 2048; i += 256) {
        int dd = i >> 7, s = i & 127;
        s_d[i] = d_src[(dg0+dd)*4096 + l0 + s];
        s_u[i] = u_src[(dg0+dd)*4096 + l0 + s];
    }
    __syncthreads();
    float h = g_h0[((dir*4+b)*32 + chunk)*2048 + d*16 + n];
    const float* pd = &s_d[dloc*128];
    const float* pu = &s_u[dloc*128];
    float* pbase = &s_p[wid*672 + ch*336];

    for (int sb = 0; sb < 128; sb += 16) {
        #pragma unroll
        for (int s4 = 0; s4 < 16; s4 += 4) {
            float4 d4 = *(const float4*)&pd[sb + s4];
            float4 u4 = *(const float4*)&pu[sb + s4];
            float dl[4] = {d4.x, d4.y, d4.z, d4.w};
            float uv[4] = {u4.x, u4.y, u4.z, u4.w};
            #pragma unroll
            for (int q = 0; q < 4; q++) {
                int s = sb + s4 + q;
                float bv = s_bc[s*32 + n];
                float cv = s_bc[s*32 + 16 + n];
                float dA = ex2f_(dl[q] * A2);
                h = fmaf(dA, h, dl[q] * bv * uv[q]);
                pbase[(s4+q)*20 + n] = h * cv;
            }
        }
        __syncwarp();
        {
            const float4* pr = (const float4*)&pbase[n*20];
            float4 r0 = pr[0], r1 = pr[1], r2 = pr[2], r3 = pr[3];
            float sum = ((r0.x + r0.y) + (r0.z + r0.w))
                      + ((r1.x + r1.y) + (r1.z + r1.w))
                      + ((r2.x + r2.y) + (r2.z + r2.w))
                      + ((r3.x + r3.y) + (r3.z + r3.w));
            float uv = pu[sb + n];
            y_dst[(dg0+dloc)*4096 + l0 + sb + n] = fmaf(uv, Dv, sum);
        }
        __syncwarp();
    }
}

// ------------------------- K5: combine + out_proj (f32x2) ------------------
__global__ void k_outproj(const float* __restrict__ opw) {
    __shared__ float s_c[64*64];
    __shared__ float s_w[64*65];
    int b = blockIdx.y;
    int l0 = blockIdx.x*64;
    int tid = threadIdx.x;
    int tc = tid >> 4, tl = tid & 15;
    float2 acc[4][2] = {};
    for (int d0 = 0; d0 < 128; d0 += 64) {
        __syncthreads();
        for (int i = tid; i < 4096; i += 256) {
            int dd = i >> 6, ll = i & 63;
            int d = d0 + dd, l = l0 + ll;
            float y0 = g_y[0][(b*128+d)*4096 + l];
            float y1 = g_y[1][(b*128+d)*4096 + (4095 - l)];
            float z  = g_xz[(b*256 + 128 + d)*4096 + l];
            s_c[i] = (y0 + y1) * siluf(z);
        }
        for (int i = tid; i < 4096; i += 256) {
            int c = i >> 6, dd = i & 63;
            s_w[c*65 + dd] = opw[c*128 + d0 + dd];
        }
        __syncthreads();
        #pragma unroll 4
        for (int kk = 0; kk < 64; kk++) {
            float4 b4 = *(const float4*)&s_c[kk*64 + tl*4];
            float2 b01 = make_float2(b4.x, b4.y), b23 = make_float2(b4.z, b4.w);
            #pragma unroll
            for (int i = 0; i < 4; i++) {
                float2 a = dup2(s_w[(tc*4+i)*65 + kk]);
                fma2(acc[i][0], a, b01);
                fma2(acc[i][1], a, b23);
            }
        }
    }
    #pragma unroll
    for (int j = 0; j < 4; j++) {
        int l = l0 + tl*4 + j;
        float v0 = (j < 2) ? ((j & 1) ? acc[0][0].y : acc[0][0].x) : ((j & 1) ? acc[0][1].y : acc[0][1].x);
        float v1 = (j < 2) ? ((j & 1) ? acc[1][0].y : acc[1][0].x) : ((j & 1) ? acc[1][1].y : acc[1][1].x);
        float v2 = (j < 2) ? ((j & 1) ? acc[2][0].y : acc[2][0].x) : ((j & 1) ? acc[2][1].y : acc[2][1].x);
        float v3 = (j < 2) ? ((j & 1) ? acc[3][0].y : acc[3][0].x) : ((j & 1) ? acc[3][1].y : acc[3][1].x);
        *(float4*)&g_outp[b*262144 + l*64 + tc*4] = make_float4(v0, v1, v2, v3);
    }
}

// ------------------------- K6: conv3d 3x3x3 + bias + residual --------------
// grid (16 t, 4 b, 4 = co-half x h-half), block 256 = 32 co x 8 rows
// smem: input stage 8640 floats + per-cc weight stage 13824 floats
__global__ void k_conv3(const float* __restrict__ xres, const float* __restrict__ proj_b) {
    extern __shared__ float s[];
    float* swt = s + 8640;                // [tap27][ci16][co32]
    int t = blockIdx.x, b = blockIdx.y;
    int zz = blockIdx.z;
    int chh = zz >> 1;
    int hh0 = (zz & 1) * 8;
    int tid = threadIdx.x;
    int col = tid & 31;
    int co = chh*32 + col;
    int hg = tid >> 5;                    // 0..7: output row hh0+hg
    float2 acc[8];
    #pragma unroll
    for (int j = 0; j < 8; j++) acc[j] = make_float2(0.f, 0.f);

    for (int cc = 0; cc < 4; cc++) {      // ci chunks of 16
        __syncthreads();
        for (int i = tid; i < 8640; i += 256) {
            int ww = i % 18; int rest = i / 18;
            int hr = rest % 10; rest /= 10;
            int tt = rest % 3; int ci = rest / 3;
            int tg = t + tt - 1, hgl = hh0 + hr - 1, wg = ww - 1;
            float v = 0.f;
            if (tg >= 0 && tg < 16 && hgl >= 0 && hgl < 16 && wg >= 0 && wg < 16)
                v = g_outp[b*262144 + (cc*16+ci)*4096 + tg*256 + hgl*16 + wg];
            s[i] = v;
        }
        for (int j = tid; j < 13824; j += 256) {
            int tap = j >> 9, rest = j & 511;
            int ci = rest >> 5, c = rest & 31;
            swt[j] = g_wT[tap*4096 + (cc*16+ci)*64 + chh*32 + c];
        }
        __syncthreads();
        for (int ci = 0; ci < 16; ci++) {
            #pragma unroll
            for (int kt = 0; kt < 3; kt++) {
                float2 wp[3][3];
                #pragma unroll
                for (int kh = 0; kh < 3; kh++)
                    #pragma unroll
                    for (int kw = 0; kw < 3; kw++)
                        wp[kh][kw] = dup2(swt[((kt*3+kh)*3+kw)*512 + ci*32 + col]);
                int base = ((ci*3 + kt)*10)*18;
                #pragma unroll
                for (int kh = 0; kh < 3; kh++) {
                    const float2* rp = (const float2*)&s[base + (hg + kh)*18];
                    float2 e[9];
                    #pragma unroll
                    for (int q = 0; q < 9; q++) e[q] = rp[q];
                    float2 o[8];
                    #pragma unroll
                    for (int j = 0; j < 8; j++) o[j] = make_float2(e[j].y, e[j+1].x);
                    #pragma unroll
                    for (int j = 0; j < 8; j++) {
                        fma2(acc[j], wp[kh][0], e[j]);
                        fma2(acc[j], wp[kh][1], o[j]);
                        fma2(acc[j], wp[kh][2], e[j+1]);
                    }
                }
            }
        }
    }
    __syncthreads();
    float pb = proj_b[co];
    #pragma unroll
    for (int j = 0; j < 8; j++) {
        s[col*128 + hg*16 + 2*j    ] = acc[j].x + pb;
        s[col*128 + hg*16 + 2*j + 1] = acc[j].y + pb;
    }
    __syncthreads();
    for (int i = tid; i < 4096; i += 256) {
        int cl = i >> 7, p = i & 127;
        int gco = chh*32 + cl;
        int off = (b*64+gco)*4096 + t*256 + hh0*16 + p;
        g_x3[off] = s[i] + xres[off];
    }
}

// ------------------------- K7: 1x1x1 norm conv (f32x2) ---------------------
__global__ void k_norm(const float* __restrict__ nw, const float* __restrict__ nb,
                       float* __restrict__ out) {
    __shared__ float s_x[64*64];
    __shared__ float s_w[64*65];
    int b = blockIdx.y;
    int p0 = blockIdx.x*64;
    int tid = threadIdx.x;
    for (int i = tid; i < 4096; i += 256) {
        int ci = i >> 6, pp = i & 63;
        s_x[i] = g_x3[(b*64+ci)*4096 + p0 + pp];
    }
    for (int i = tid; i < 4096; i += 256) {
        int co = i >> 6, ci = i & 63;
        s_w[co*65 + ci] = nw[i];
    }
    __syncthreads();
    int tc = tid >> 4, tl = tid & 15;
    float2 acc[4][2] = {};
    #pragma unroll 4
    for (int k = 0; k < 64; k++) {
        float4 b4 = *(const float4*)&s_x[k*64 + tl*4];
        float2 b01 = make_float2(b4.x, b4.y), b23 = make_float2(b4.z, b4.w);
        #pragma unroll
        for (int i = 0; i < 4; i++) {
            float2 a = dup2(s_w[(tc*4+i)*65 + k]);
            fma2(acc[i][0], a, b01);
            fma2(acc[i][1], a, b23);
        }
    }
    #pragma unroll
    for (int i = 0; i < 4; i++) {
        int co = tc*4 + i;
        float bb = nb[co];
        *(float4*)&out[(b*64+co)*4096 + p0 + tl*4] =
            make_float4(acc[i][0].x + bb, acc[i][0].y + bb,
                        acc[i][1].x + bb, acc[i][1].y + bb);
    }
}

// ------------------------- launch ------------------------------------------
extern "C" void kernel_launch(void* const* d_in, const int* in_sizes, int n_in,
                              void* d_out, int out_size) {
    const float* x    = (const float*)d_in[0];
    const float* ipw  = (const float*)d_in[1];
    const float* cw0  = (const float*)d_in[2];
    const float* cb0  = (const float*)d_in[3];
    const float* xpw0 = (const float*)d_in[4];
    const float* dtw0 = (const float*)d_in[5];
    const float* dtb0 = (const float*)d_in[6];
    const float* Al0  = (const float*)d_in[7];
    const float* D0   = (const float*)d_in[8];
    const float* cw1  = (const float*)d_in[9];
    const float* cb1  = (const float*)d_in[10];
    const float* xpw1 = (const float*)d_in[11];
    const float* dtw1 = (const float*)d_in[12];
    const float* dtb1 = (const float*)d_in[13];
    const float* Al1  = (const float*)d_in[14];
    const float* D1   = (const float*)d_in[15];
    const float* opw  = (const float*)d_in[16];
    const float* pw   = (const float*)d_in[17];
    const float* pb   = (const float*)d_in[18];
    const float* nw   = (const float*)d_in[19];
    const float* nb   = (const float*)d_in[20];
    float* out = (float*)d_out;

    cudaFuncSetAttribute(k_conv3, cudaFuncAttributeMaxDynamicSharedMemorySize, (8640+13824)*4);

    k_prep   <<< (2*160*128 + 27*4096 + 255)/256, 256 >>>(xpw0, dtw0, xpw1, dtw1, pw);
    k_inproj <<< dim3(64, 4, 4), 256 >>>(x, ipw);
    k_conv   <<< (1<<22)/256, 256 >>>(cw0, cb0, cw1, cb1);
    k_xproj  <<< dim3(16, 5, 8), 256 >>>(dtb0, dtb1);
    k_scanA  <<< dim3(256, 4, 2), 256 >>>(Al0, Al1);
    k_scanB  <<< dim3(8, 8), 256 >>>();
    k_scanC  <<< dim3(256, 4, 2), 256 >>>(Al0, D0, Al1, D1);
    k_outproj<<< dim3(64, 4), 256 >>>(opw);
    k_conv3  <<< dim3(16, 4, 4), 256, (8640+13824)*4 >>>(x, pb);
    k_norm   <<< dim3(64, 4), 256 >>>(nw, nb, out);
}

// round 17
// speedup vs baseline: 1.0543x; 1.0173x over previous
#include <cuda_runtime.h>

#define LSEQ 4096

// ----------------------------- scratch ------------------------------------
__device__ float g_xz[4*256*LSEQ];        // in_proj output (b, 2d, l)
__device__ float g_xc[2][4*128*LSEQ];     // conv+silu per dir (dir1 in flipped space)
__device__ float g_BC[2][4*LSEQ*32];      // (b, l, [Bm16|Cm16]) transposed for scan
__device__ float g_delta[2][4*128*LSEQ];  // softplus(dt@dtproj + b)
__device__ float g_y[2][4*128*LSEQ];      // scan outputs per dir
__device__ float g_outp[4*LSEQ*64];       // out_proj result (b, l, c) == x_recon
__device__ float g_x3[4*64*LSEQ];         // conv3d + bias + residual
__device__ float g_Wf[2][128*160];        // fused weights, K-MAJOR: [dir][k*160+e]
__device__ float g_wT[27*64*64];          // proj_w transposed [tap][ci][co]
__device__ float g_P[2*4*32*2048];        // chunk transfer: product of dA
__device__ float g_q[2*4*32*2048];        // chunk transfer: local final state
__device__ float g_h0[2*4*32*2048];       // per-chunk starting state

__device__ __forceinline__ float ex2f_(float x) {
    float y; asm("ex2.approx.ftz.f32 %0, %1;" : "=f"(y) : "f"(x)); return y;
}
__device__ __forceinline__ float lg2f_(float x) {
    float y; asm("lg2.approx.f32 %0, %1;" : "=f"(y) : "f"(x)); return y;
}
__device__ __forceinline__ float siluf(float v) {
    return __fdividef(v, 1.f + ex2f_(-1.44269504f * v));
}

// packed dual-FMA (Blackwell f32x2): d = a*b + d
__device__ __forceinline__ void fma2(float2& d, const float2& a, const float2& b) {
    unsigned long long& du = reinterpret_cast<unsigned long long&>(d);
    const unsigned long long& au = reinterpret_cast<const unsigned long long&>(a);
    const unsigned long long& bu = reinterpret_cast<const unsigned long long&>(b);
    asm("fma.rn.f32x2 %0, %1, %2, %0;" : "+l"(du) : "l"(au), "l"(bu));
}
__device__ __forceinline__ float2 dup2(float a) { return make_float2(a, a); }

// ------------------------- K0: weight prep --------------------------------
__global__ void k_prep(const float* __restrict__ xp0, const float* __restrict__ dt0,
                       const float* __restrict__ xp1, const float* __restrict__ dt1,
                       const float* __restrict__ proj_w) {
    int idx = blockIdx.x*256 + threadIdx.x;
    const int NWF = 2*160*128;
    if (idx < NWF) {
        int dir = idx / (160*128);
        int r = idx % (160*128);
        int e = r >> 7, k = r & 127;
        const float* xp = dir ? xp1 : xp0;
        float v;
        if (e < 32) {
            v = xp[(8+e)*128 + k];                     // rows 8..39 of x_dbl = Bm,Cm
        } else {
            const float* dtw = dir ? dt1 : dt0;
            int d = e - 32; v = 0.f;
            #pragma unroll
            for (int rr = 0; rr < 8; rr++) v = fmaf(dtw[d*8+rr], xp[rr*128+k], v);
        }
        g_Wf[dir][k*160 + e] = v;                      // K-MAJOR
    } else if (idx < NWF + 27*4096) {
        int j = idx - NWF;
        int tap = j >> 12, rest = j & 4095;
        int ci = rest >> 6, co = rest & 63;
        g_wT[j] = proj_w[(co*64 + ci)*27 + tap];       // [tap][ci][co]
    }
}

// ------------------------- K1: in_proj GEMM with seq gather ----------------
__global__ void k_inproj(const float* __restrict__ x, const float* __restrict__ W) {
    __shared__ float S[64*64];      // [c][l_local]
    __shared__ float Wt[64*65];     // [e][c] padded
    int b = blockIdx.z, e0 = blockIdx.y*64, l0 = blockIdx.x*64;
    int h = l0 >> 8, w0 = (l0 >> 4) & 15;
    int tid = threadIdx.x;
    // gather: one float4 per (c,t) covers wl=0..3 (w0 multiple of 4 -> aligned)
    for (int i = tid; i < 1024; i += 256) {
        int c = i >> 4, t = i & 15;
        float4 v = *(const float4*)&x[(b*64+c)*4096 + t*256 + h*16 + w0];
        S[c*64 +      t] = v.x;
        S[c*64 + 16 + t] = v.y;
        S[c*64 + 32 + t] = v.z;
        S[c*64 + 48 + t] = v.w;
    }
    for (int i = tid; i < 4096; i += 256) {
        int e = i >> 6, c = i & 63;
        Wt[e*65 + c] = W[(e0+e)*64 + c];
    }
    __syncthreads();
    int te = tid >> 4, tl = tid & 15;
    float2 acc[4][2] = {};
    #pragma unroll 4
    for (int k = 0; k < 64; k++) {
        float4 b4 = *(const float4*)&S[k*64 + tl*4];
        float2 b01 = make_float2(b4.x, b4.y), b23 = make_float2(b4.z, b4.w);
        #pragma unroll
        for (int i = 0; i < 4; i++) {
            float2 a = dup2(Wt[(te*4+i)*65 + k]);
            fma2(acc[i][0], a, b01);
            fma2(acc[i][1], a, b23);
        }
    }
    #pragma unroll
    for (int i = 0; i < 4; i++) {
        int e = e0 + te*4 + i;
        *(float4*)&g_xz[(b*256+e)*4096 + l0 + tl*4] =
            make_float4(acc[i][0].x, acc[i][0].y, acc[i][1].x, acc[i][1].y);
    }
}

// ------------------------- K2: causal dwconv + silu (4 l / thread) ---------
__global__ void k_conv(const float* __restrict__ cw0, const float* __restrict__ cb0,
                       const float* __restrict__ cw1, const float* __restrict__ cb1) {
    int idx = blockIdx.x*256 + threadIdx.x;      // 2^20 total
    int l4  = (idx & 1023) * 4;
    int d   = (idx >> 10) & 127;
    int b   = (idx >> 17) & 3;
    int dir = idx >> 19;
    const float* row = g_xz + (b*256 + d)*4096;
    const float* cw = dir ? cw1 : cw0;
    float w0 = cw[d*4], w1 = cw[d*4+1], w2 = cw[d*4+2], w3 = cw[d*4+3];
    float bias = (dir ? cb1 : cb0)[d];
    float v[4];
    if (dir == 0) {
        float4 A = (l4 >= 4) ? *(const float4*)&row[l4-4] : make_float4(0,0,0,0);
        float4 C = *(const float4*)&row[l4];
        float xm[8] = {A.x, A.y, A.z, A.w, C.x, C.y, C.z, C.w};   // l4-4 .. l4+3
        #pragma unroll
        for (int j = 0; j < 4; j++)
            v[j] = bias + w0*xm[j+1] + w1*xm[j+2] + w2*xm[j+3] + w3*xm[j+4];
    } else {
        int m = 4092 - l4;                    // row[m..m+6] needed (descending seq)
        float4 A = *(const float4*)&row[m];
        float4 C = (l4 >= 4) ? *(const float4*)&row[m+4] : make_float4(0,0,0,0);
        float ym[8] = {A.x, A.y, A.z, A.w, C.x, C.y, C.z, C.w};   // row[4092-l4 + i]
        #pragma unroll
        for (int j = 0; j < 4; j++)
            v[j] = bias + w0*ym[6-j] + w1*ym[5-j] + w2*ym[4-j] + w3*ym[3-j];
    }
    *(float4*)&g_xc[dir][(b*128+d)*4096 + l4] =
        make_float4(siluf(v[0]), siluf(v[1]), siluf(v[2]), siluf(v[3]));
}

// ------------------------- K3: fused xproj/dtproj GEMM (8r x 4l tile) ------
__global__ void __launch_bounds__(256, 3)
k_xproj(const float* __restrict__ dtb0, const float* __restrict__ dtb1) {
    __shared__ float s_w[32*64];    // [k][r*2 + {0,1}] duplicated
    __shared__ float s_x[32*256];   // [k][l]
    int db = blockIdx.z;            // dir*4 + b
    int dir = db >> 2, b = db & 3;
    int r0 = blockIdx.y * 32;
    int l0 = blockIdx.x * 256;
    int tid = threadIdx.x;
    int tr = tid >> 6, tl = tid & 63;
    float2 acc[8][2] = {};
    for (int kc = 0; kc < 128; kc += 32) {
        __syncthreads();
        for (int i = tid; i < 2048; i += 256) {
            int k = i >> 6, rr = i & 63;
            s_w[i] = g_Wf[dir][(kc+k)*160 + r0 + (rr >> 1)];
        }
        for (int i = tid*4; i < 8192; i += 1024) {
            int k = i >> 8, ll = i & 255;
            *(float4*)&s_x[i] = *(const float4*)&g_xc[dir][(b*128 + kc + k)*4096 + l0 + ll];
        }
        __syncthreads();
        #pragma unroll 8
        for (int k = 0; k < 32; k++) {
            float4 b4 = *(const float4*)&s_x[k*256 + tl*4];
            float2 bp0 = make_float2(b4.x, b4.y);
            float2 bp1 = make_float2(b4.z, b4.w);
            const float4* wa = (const float4*)&s_w[k*64 + tr*16];
            float4 w0 = wa[0], w1 = wa[1], w2 = wa[2], w3 = wa[3];
            float2 a0 = make_float2(w0.x, w0.y), a1 = make_float2(w0.z, w0.w);
            float2 a2 = make_float2(w1.x, w1.y), a3 = make_float2(w1.z, w1.w);
            float2 a4 = make_float2(w2.x, w2.y), a5 = make_float2(w2.z, w2.w);
            float2 a6 = make_float2(w3.x, w3.y), a7 = make_float2(w3.z, w3.w);
            fma2(acc[0][0], a0, bp0); fma2(acc[0][1], a0, bp1);
            fma2(acc[1][0], a1, bp0); fma2(acc[1][1], a1, bp1);
            fma2(acc[2][0], a2, bp0); fma2(acc[2][1], a2, bp1);
            fma2(acc[3][0], a3, bp0); fma2(acc[3][1], a3, bp1);
            fma2(acc[4][0], a4, bp0); fma2(acc[4][1], a4, bp1);
            fma2(acc[5][0], a5, bp0); fma2(acc[5][1], a5, bp1);
            fma2(acc[6][0], a6, bp0); fma2(acc[6][1], a6, bp1);
            fma2(acc[7][0], a7, bp0); fma2(acc[7][1], a7, bp1);
        }
    }
    const float* dtb = dir ? dtb1 : dtb0;
    int lb = l0 + tl*4;
    if (r0 == 0) {
        #pragma unroll
        for (int i = 0; i < 8; i++) {
            int rg = tr*8 + i;
            float vv[4] = {acc[i][0].x, acc[i][0].y, acc[i][1].x, acc[i][1].y};
            #pragma unroll
            for (int j = 0; j < 4; j++)
                g_BC[dir][(b*4096 + lb + j)*32 + rg] = vv[j];
        }
    } else {
        #pragma unroll
        for (int i = 0; i < 8; i++) {
            int d = r0 + tr*8 + i - 32;
            float bias = dtb[d];
            float vv[4] = {acc[i][0].x, acc[i][0].y, acc[i][1].x, acc[i][1].y};
            #pragma unroll
            for (int j = 0; j < 4; j++) {
                float sarg = vv[j] + bias;
                vv[j] = (sarg > 20.f) ? sarg
                      : 0.69314718056f * lg2f_(1.f + ex2f_(sarg * 1.44269504f));
            }
            *(float4*)&g_delta[dir][(b*128+d)*4096 + lb] =
                make_float4(vv[0], vv[1], vv[2], vv[3]);
        }
    }
}

// ------------------------- K4a: scan pass A (chunk transfer fns) ------------
__global__ void k_scanA(const float* __restrict__ Al0, const float* __restrict__ Al1) {
    __shared__ float s_b[128*16];
    __shared__ float s_d[16*128];
    __shared__ float s_u[16*128];
    int chunk = blockIdx.x >> 3;
    int dg0 = (blockIdx.x & 7) * 16;
    int b = blockIdx.y, dir = blockIdx.z;
    int l0 = chunk * 128;
    int tid = threadIdx.x;
    int wid = tid >> 5, lane = tid & 31;
    int ch = lane >> 4, n = lane & 15;
    int dloc = wid*2 + ch;
    int d = dg0 + dloc;
    const float* Alog = dir ? Al1 : Al0;
    float A2 = -__expf(Alog[d*16 + n]) * 1.44269504089f;
    const float* bc_src = g_BC[dir]    + b*4096*32 + l0*32;
    const float* d_src  = g_delta[dir] + b*128*4096;
    const float* u_src  = g_xc[dir]    + b*128*4096;
    for (int i = tid; i < 2048; i += 256) s_b[i] = bc_src[(i >> 4)*32 + (i & 15)];
    for (int i = tid; i < 2048; i += 256) {
        int dd = i >> 7, s = i & 127;
        s_d[i] = d_src[(dg0+dd)*4096 + l0 + s];
        s_u[i] = u_src[(dg0+dd)*4096 + l0 + s];
    }
    __syncthreads();
    float h = 0.f, P = 1.f;
    const float* pd = &s_d[dloc*128];
    const float* pu = &s_u[dloc*128];
    for (int s4 = 0; s4 < 128; s4 += 4) {
        float4 d4 = *(const float4*)&pd[s4];
        float4 u4 = *(const float4*)&pu[s4];
        float dl[4] = {d4.x, d4.y, d4.z, d4.w};
        float uv[4] = {u4.x, u4.y, u4.z, u4.w};
        #pragma unroll
        for (int q = 0; q < 4; q++) {
            float bv = s_b[(s4+q)*16 + n];
            float dA = ex2f_(dl[q] * A2);
            h = fmaf(dA, h, dl[q] * bv * uv[q]);
            P *= dA;
        }
    }
    int idx = ((dir*4+b)*32 + chunk)*2048 + d*16 + n;
    g_P[idx] = P;
    g_q[idx] = h;
}

// ------------------------- K4b: scan pass B (cross-chunk combine) -----------
__global__ void k_scanB() {
    int db = blockIdx.y;
    int dn = blockIdx.x*256 + threadIdx.x;
    int base = db*32*2048 + dn;
    float h = 0.f;
    #pragma unroll
    for (int c = 0; c < 32; c++) {
        g_h0[base + c*2048] = h;
        h = fmaf(g_P[base + c*2048], h, g_q[base + c*2048]);
    }
}

// ------------------------- K4c: scan pass C (replay, smem-batched reduce) ---
__global__ void k_scanC(const float* __restrict__ Al0, const float* __restrict__ Dp0,
                        const float* __restrict__ Al1, const float* __restrict__ Dp1) {
    __shared__ float s_bc[128*32];
    __shared__ float s_d[16*128];
    __shared__ float s_u[16*128];
    __shared__ float s_p[8*672];
    int chunk = blockIdx.x >> 3;
    int dg0 = (blockIdx.x & 7) * 16;
    int b = blockIdx.y, dir = blockIdx.z;
    int l0 = chunk * 128;
    int tid = threadIdx.x;
    int wid = tid >> 5, lane = tid & 31;
    int ch = lane >> 4, n = lane & 15;
    int dloc = wid*2 + ch;
    int d = dg0 + dloc;
    const float* Alog = dir ? Al1 : Al0;
    const float* Dp   = dir ? Dp1 : Dp0;
    float A2 = -__expf(Alog[d*16 + n]) * 1.44269504089f;
    float Dv = Dp[d];
    const float* bc_src = g_BC[dir]    + b*4096*32 + l0*32;
    const float* d_src  = g_delta[dir] + b*128*4096;
    const float* u_src  = g_xc[dir]    + b*128*4096;
    float*       y_dst  = g_y[dir]     + b*128*4096;
    for (int i = tid; i < 4096; i += 256) s_bc[i] = bc_src[i];
    for (int i = tid; i < 2048; i += 256) {
        int dd = i >> 7, s = i & 127;
        s_d[i] = d_src[(dg0+dd)*4096 + l0 + s];
        s_u[i] = u_src[(dg0+dd)*4096 + l0 + s];
    }
    __syncthreads();
    float h = g_h0[((dir*4+b)*32 + chunk)*2048 + d*16 + n];
    const float* pd = &s_d[dloc*128];
    const float* pu = &s_u[dloc*128];
    float* pbase = &s_p[wid*672 + ch*336];

    for (int sb = 0; sb < 128; sb += 16) {
        #pragma unroll
        for (int s4 = 0; s4 < 16; s4 += 4) {
            float4 d4 = *(const float4*)&pd[sb + s4];
            float4 u4 = *(const float4*)&pu[sb + s4];
            float dl[4] = {d4.x, d4.y, d4.z, d4.w};
            float uv[4] = {u4.x, u4.y, u4.z, u4.w};
            #pragma unroll
            for (int q = 0; q < 4; q++) {
                int s = sb + s4 + q;
                float bv = s_bc[s*32 + n];
                float cv = s_bc[s*32 + 16 + n];
                float dA = ex2f_(dl[q] * A2);
                h = fmaf(dA, h, dl[q] * bv * uv[q]);
                pbase[(s4+q)*20 + n] = h * cv;
            }
        }
        __syncwarp();
        {
            const float4* pr = (const float4*)&pbase[n*20];
            float4 r0 = pr[0], r1 = pr[1], r2 = pr[2], r3 = pr[3];
            float sum = ((r0.x + r0.y) + (r0.z + r0.w))
                      + ((r1.x + r1.y) + (r1.z + r1.w))
                      + ((r2.x + r2.y) + (r2.z + r2.w))
                      + ((r3.x + r3.y) + (r3.z + r3.w));
            float uv = pu[sb + n];
            y_dst[(dg0+dloc)*4096 + l0 + sb + n] = fmaf(uv, Dv, sum);
        }
        __syncwarp();
    }
}

// ------------------------- K5: combine + out_proj (f32x2) ------------------
__global__ void k_outproj(const float* __restrict__ opw) {
    __shared__ float s_c[64*64];
    __shared__ float s_w[64*65];
    int b = blockIdx.y;
    int l0 = blockIdx.x*64;
    int tid = threadIdx.x;
    int tc = tid >> 4, tl = tid & 15;
    float2 acc[4][2] = {};
    for (int d0 = 0; d0 < 128; d0 += 64) {
        __syncthreads();
        for (int i = tid; i < 4096; i += 256) {
            int dd = i >> 6, ll = i & 63;
            int d = d0 + dd, l = l0 + ll;
            float y0 = g_y[0][(b*128+d)*4096 + l];
            float y1 = g_y[1][(b*128+d)*4096 + (4095 - l)];
            float z  = g_xz[(b*256 + 128 + d)*4096 + l];
            s_c[i] = (y0 + y1) * siluf(z);
        }
        for (int i = tid; i < 4096; i += 256) {
            int c = i >> 6, dd = i & 63;
            s_w[c*65 + dd] = opw[c*128 + d0 + dd];
        }
        __syncthreads();
        #pragma unroll 4
        for (int kk = 0; kk < 64; kk++) {
            float4 b4 = *(const float4*)&s_c[kk*64 + tl*4];
            float2 b01 = make_float2(b4.x, b4.y), b23 = make_float2(b4.z, b4.w);
            #pragma unroll
            for (int i = 0; i < 4; i++) {
                float2 a = dup2(s_w[(tc*4+i)*65 + kk]);
                fma2(acc[i][0], a, b01);
                fma2(acc[i][1], a, b23);
            }
        }
    }
    #pragma unroll
    for (int j = 0; j < 4; j++) {
        int l = l0 + tl*4 + j;
        float v0 = (j < 2) ? ((j & 1) ? acc[0][0].y : acc[0][0].x) : ((j & 1) ? acc[0][1].y : acc[0][1].x);
        float v1 = (j < 2) ? ((j & 1) ? acc[1][0].y : acc[1][0].x) : ((j & 1) ? acc[1][1].y : acc[1][1].x);
        float v2 = (j < 2) ? ((j & 1) ? acc[2][0].y : acc[2][0].x) : ((j & 1) ? acc[2][1].y : acc[2][1].x);
        float v3 = (j < 2) ? ((j & 1) ? acc[3][0].y : acc[3][0].x) : ((j & 1) ? acc[3][1].y : acc[3][1].x);
        *(float4*)&g_outp[b*262144 + l*64 + tc*4] = make_float4(v0, v1, v2, v3);
    }
}

// ------------------------- K6: conv3d 3x3x3 + bias + residual --------------
// grid (16 t, 4 b, 4 = co-half x h-half), block 256 = 32 co x 8 rows
// smem: input stage 8640 floats + per-cc weight stage 13824 floats
__global__ void k_conv3(const float* __restrict__ xres, const float* __restrict__ proj_b) {
    extern __shared__ float s[];
    float* swt = s + 8640;                // [tap27][ci16][co32]
    int t = blockIdx.x, b = blockIdx.y;
    int zz = blockIdx.z;
    int chh = zz >> 1;
    int hh0 = (zz & 1) * 8;
    int tid = threadIdx.x;
    int col = tid & 31;
    int co = chh*32 + col;
    int hg = tid >> 5;                    // 0..7: output row hh0+hg
    float2 acc[8];
    #pragma unroll
    for (int j = 0; j < 8; j++) acc[j] = make_float2(0.f, 0.f);

    for (int cc = 0; cc < 4; cc++) {      // ci chunks of 16
        __syncthreads();
        for (int i = tid; i < 8640; i += 256) {
            int ww = i % 18; int rest = i / 18;
            int hr = rest % 10; rest /= 10;
            int tt = rest % 3; int ci = rest / 3;
            int tg = t + tt - 1, hgl = hh0 + hr - 1, wg = ww - 1;
            float v = 0.f;
            if (tg >= 0 && tg < 16 && hgl >= 0 && hgl < 16 && wg >= 0 && wg < 16)
                v = g_outp[b*262144 + (cc*16+ci)*4096 + tg*256 + hgl*16 + wg];
            s[i] = v;
        }
        for (int j = tid; j < 13824; j += 256) {
            int tap = j >> 9, rest = j & 511;
            int ci = rest >> 5, c = rest & 31;
            swt[j] = g_wT[tap*4096 + (cc*16+ci)*64 + chh*32 + c];
        }
        __syncthreads();
        for (int ci = 0; ci < 16; ci++) {
            #pragma unroll
            for (int kt = 0; kt < 3; kt++) {
                float2 wp[3][3];
                #pragma unroll
                for (int kh = 0; kh < 3; kh++)
                    #pragma unroll
                    for (int kw = 0; kw < 3; kw++)
                        wp[kh][kw] = dup2(swt[((kt*3+kh)*3+kw)*512 + ci*32 + col]);
                int base = ((ci*3 + kt)*10)*18;
                #pragma unroll
                for (int kh = 0; kh < 3; kh++) {
                    const float2* rp = (const float2*)&s[base + (hg + kh)*18];
                    float2 e[9];
                    #pragma unroll
                    for (int q = 0; q < 9; q++) e[q] = rp[q];
                    float2 o[8];
                    #pragma unroll
                    for (int j = 0; j < 8; j++) o[j] = make_float2(e[j].y, e[j+1].x);
                    #pragma unroll
                    for (int j = 0; j < 8; j++) {
                        fma2(acc[j], wp[kh][0], e[j]);
                        fma2(acc[j], wp[kh][1], o[j]);
                        fma2(acc[j], wp[kh][2], e[j+1]);
                    }
                }
            }
        }
    }
    __syncthreads();
    float pb = proj_b[co];
    #pragma unroll
    for (int j = 0; j < 8; j++) {
        s[col*128 + hg*16 + 2*j    ] = acc[j].x + pb;
        s[col*128 + hg*16 + 2*j + 1] = acc[j].y + pb;
    }
    __syncthreads();
    for (int i = tid; i < 4096; i += 256) {
        int cl = i >> 7, p = i & 127;
        int gco = chh*32 + cl;
        int off = (b*64+gco)*4096 + t*256 + hh0*16 + p;
        g_x3[off] = s[i] + xres[off];
    }
}

// ------------------------- K7: 1x1x1 norm conv (f32x2) ---------------------
__global__ void k_norm(const float* __restrict__ nw, const float* __restrict__ nb,
                       float* __restrict__ out) {
    __shared__ float s_x[64*64];
    __shared__ float s_w[64*65];
    int b = blockIdx.y;
    int p0 = blockIdx.x*64;
    int tid = threadIdx.x;
    for (int i = tid; i < 4096; i += 256) {
        int ci = i >> 6, pp = i & 63;
        s_x[i] = g_x3[(b*64+ci)*4096 + p0 + pp];
    }
    for (int i = tid; i < 4096; i += 256) {
        int co = i >> 6, ci = i & 63;
        s_w[co*65 + ci] = nw[i];
    }
    __syncthreads();
    int tc = tid >> 4, tl = tid & 15;
    float2 acc[4][2] = {};
    #pragma unroll 4
    for (int k = 0; k < 64; k++) {
        float4 b4 = *(const float4*)&s_x[k*64 + tl*4];
        float2 b01 = make_float2(b4.x, b4.y), b23 = make_float2(b4.z, b4.w);
        #pragma unroll
        for (int i = 0; i < 4; i++) {
            float2 a = dup2(s_w[(tc*4+i)*65 + k]);
            fma2(acc[i][0], a, b01);
            fma2(acc[i][1], a, b23);
        }
    }
    #pragma unroll
    for (int i = 0; i < 4; i++) {
        int co = tc*4 + i;
        float bb = nb[co];
        *(float4*)&out[(b*64+co)*4096 + p0 + tl*4] =
            make_float4(acc[i][0].x + bb, acc[i][0].y + bb,
                        acc[i][1].x + bb, acc[i][1].y + bb);
    }
}

// ------------------------- launch ------------------------------------------
extern "C" void kernel_launch(void* const* d_in, const int* in_sizes, int n_in,
                              void* d_out, int out_size) {
    const float* x    = (const float*)d_in[0];
    const float* ipw  = (const float*)d_in[1];
    const float* cw0  = (const float*)d_in[2];
    const float* cb0  = (const float*)d_in[3];
    const float* xpw0 = (const float*)d_in[4];
    const float* dtw0 = (const float*)d_in[5];
    const float* dtb0 = (const float*)d_in[6];
    const float* Al0  = (const float*)d_in[7];
    const float* D0   = (const float*)d_in[8];
    const float* cw1  = (const float*)d_in[9];
    const float* cb1  = (const float*)d_in[10];
    const float* xpw1 = (const float*)d_in[11];
    const float* dtw1 = (const float*)d_in[12];
    const float* dtb1 = (const float*)d_in[13];
    const float* Al1  = (const float*)d_in[14];
    const float* D1   = (const float*)d_in[15];
    const float* opw  = (const float*)d_in[16];
    const float* pw   = (const float*)d_in[17];
    const float* pb   = (const float*)d_in[18];
    const float* nw   = (const float*)d_in[19];
    const float* nb   = (const float*)d_in[20];
    float* out = (float*)d_out;

    cudaFuncSetAttribute(k_conv3, cudaFuncAttributeMaxDynamicSharedMemorySize, (8640+13824)*4);

    k_prep   <<< (2*160*128 + 27*4096 + 255)/256, 256 >>>(xpw0, dtw0, xpw1, dtw1, pw);
    k_inproj <<< dim3(64, 4, 4), 256 >>>(x, ipw);
    k_conv   <<< (1<<20)/256, 256 >>>(cw0, cb0, cw1, cb1);
    k_xproj  <<< dim3(16, 5, 8), 256 >>>(dtb0, dtb1);
    k_scanA  <<< dim3(256, 4, 2), 256 >>>(Al0, Al1);
    k_scanB  <<< dim3(8, 8), 256 >>>();
    k_scanC  <<< dim3(256, 4, 2), 256 >>>(Al0, D0, Al1, D1);
    k_outproj<<< dim3(64, 4), 256 >>>(opw);
    k_conv3  <<< dim3(16, 4, 4), 256, (8640+13824)*4 >>>(x, pb);
    k_norm   <<< dim3(64, 4), 256 >>>(nw, nb, out);
}